// round 3
// baseline (speedup 1.0000x reference)
#include <cuda_runtime.h>
#include <cuda_bf16.h>

// ============================================================================
// BlockG: StyleGAN2-ish synthesis block, fp32 baseline.
//   x   [8,512,32,32] -> up2 -> conv3x3(mod/demod) -> leaky -> conv3x3 -> leaky
//   rgb [8,3,32,32]   -> up2 -> + leaky(conv1x1(x2))
// Modulated conv rewritten as: scale input by style, shared-weight conv,
// scale output by demod factor.
// Output layout: d_out[0 : 8*512*64*64) = x, then d_out[... : +8*3*64*64) = rgb
// ============================================================================

#define B_ 8
#define C_ 512
#define HI 32
#define WI 32
#define HO 64
#define WO 64
#define PIX (HO*WO)           // 4096
#define XEL (B_*C_*PIX)       // 16777216
#define EPSV 1e-8f
#define SLOPE 0.2f

// ---------------- device scratch (static globals: allocation-free) ----------
__device__ float g_xup[XEL];          // up2(x) * s1
__device__ float g_y1 [XEL];          // leaky(conv1) * s2
__device__ float g_w1t[C_*9*C_];      // weight1 transposed [ci][tap][co]
__device__ float g_w2t[C_*9*C_];
__device__ float g_w2s1[C_*C_];       // sum_k w1^2 [co][ci]
__device__ float g_w2s2[C_*C_];
__device__ float g_s1[B_*C_], g_s2[B_*C_], g_s3[B_*C_];
__device__ float g_d1[B_*C_], g_d2[B_*C_];
__device__ float g_m3[B_*3*C_];       // w3*s3*d3

// ---------------- styles: s[b,i] = dot(w[b,:], A[i,:]) + bias[i] ------------
__global__ void k_styles(const float* __restrict__ w,
                         const float* __restrict__ A1, const float* __restrict__ b1,
                         const float* __restrict__ A2, const float* __restrict__ b2,
                         const float* __restrict__ A3, const float* __restrict__ b3)
{
    int gw = (blockIdx.x * blockDim.x + threadIdx.x) >> 5;   // global warp id
    int lane = threadIdx.x & 31;
    if (gw >= 3 * B_ * C_) return;
    int m = gw / (B_ * C_);
    int r = gw - m * (B_ * C_);
    int b = r >> 9, i = r & 511;
    const float* A  = (m == 0) ? A1 : (m == 1) ? A2 : A3;
    const float* bs = (m == 0) ? b1 : (m == 1) ? b2 : b3;
    float acc = 0.f;
    const float* wb = w + b * C_;
    const float* Ai = A + i * C_;
    for (int k = lane; k < C_; k += 32) acc += wb[k] * Ai[k];
    #pragma unroll
    for (int o = 16; o > 0; o >>= 1) acc += __shfl_xor_sync(0xffffffffu, acc, o);
    if (lane == 0) {
        float v = acc + bs[i];
        float* out = (m == 0) ? g_s1 : (m == 1) ? g_s2 : g_s3;
        out[b * C_ + i] = v;
    }
}

// ---------------- weight prep: sumsq + transpose ----------------------------
__global__ void k_wprep(const float* __restrict__ w1, const float* __restrict__ w2)
{
    int idx = blockIdx.x * blockDim.x + threadIdx.x;
    if (idx >= 2 * C_ * C_) return;
    int m = idx >> 18;
    int r = idx & (C_ * C_ - 1);
    int co = r >> 9, ci = r & 511;
    const float* w = m ? w2 : w1;
    float* wt  = m ? g_w2t  : g_w1t;
    float* w2s = m ? g_w2s2 : g_w2s1;
    const float* src = w + (size_t)(co * C_ + ci) * 9;
    float ss = 0.f;
    #pragma unroll
    for (int t = 0; t < 9; t++) {
        float v = src[t];
        ss += v * v;
        wt[(ci * 9 + t) * C_ + co] = v;
    }
    w2s[co * C_ + ci] = ss;
}

// ---------------- demod: d[b,co] = rsqrt(sum_ci w2s*s^2 + eps) --------------
__global__ void k_demod()
{
    int gw = (blockIdx.x * blockDim.x + threadIdx.x) >> 5;
    int lane = threadIdx.x & 31;
    if (gw >= 2 * B_ * C_) return;
    int m = gw >> 12;
    int r = gw & 4095;
    int b = r >> 9, co = r & 511;
    const float* w2s = m ? g_w2s2 : g_w2s1;
    const float* s   = m ? g_s2   : g_s1;
    float acc = 0.f;
    const float* wr = w2s + co * C_;
    const float* sr = s + b * C_;
    for (int ci = lane; ci < C_; ci += 32) { float sv = sr[ci]; acc += wr[ci] * sv * sv; }
    #pragma unroll
    for (int o = 16; o > 0; o >>= 1) acc += __shfl_xor_sync(0xffffffffu, acc, o);
    if (lane == 0) {
        float* d = m ? g_d2 : g_d1;
        d[b * C_ + co] = rsqrtf(acc + EPSV);
    }
}

// ---------------- toRGB modulation: m3 = w3*s3*d3 ---------------------------
__global__ void k_m3(const float* __restrict__ w3)
{
    int b = blockIdx.x / 3, j = blockIdx.x % 3;
    __shared__ float red[128];
    __shared__ float d3s;
    int tid = threadIdx.x;
    float acc = 0.f;
    for (int ci = tid; ci < C_; ci += 128) {
        float t = w3[j * C_ + ci] * g_s3[b * C_ + ci];
        acc += t * t;
    }
    red[tid] = acc; __syncthreads();
    for (int o = 64; o > 0; o >>= 1) { if (tid < o) red[tid] += red[tid + o]; __syncthreads(); }
    if (tid == 0) d3s = rsqrtf(red[0] + EPSV);
    __syncthreads();
    float d3 = d3s;
    for (int ci = tid; ci < C_; ci += 128)
        g_m3[(b * 3 + j) * C_ + ci] = w3[j * C_ + ci] * g_s3[b * C_ + ci] * d3;
}

// ---------------- upsample x2 (align_corners) + style scale -----------------
__device__ __forceinline__ float bilerp32(const float* __restrict__ p, int y, int x)
{
    const float F = 31.0f / 63.0f;
    float cy = (float)y * F, cx = (float)x * F;
    int iy0 = (int)cy, ix0 = (int)cx;
    float ty = cy - (float)iy0, tx = cx - (float)ix0;
    int iy1 = min(iy0 + 1, 31), ix1 = min(ix0 + 1, 31);
    float v00 = p[iy0 * 32 + ix0], v01 = p[iy0 * 32 + ix1];
    float v10 = p[iy1 * 32 + ix0], v11 = p[iy1 * 32 + ix1];
    // reference order: interpolate along H first, then W
    float a = v00 * (1.f - ty) + v10 * ty;
    float c = v01 * (1.f - ty) + v11 * ty;
    return a * (1.f - tx) + c * tx;
}

__global__ void k_upx(const float* __restrict__ xin)
{
    int idx = blockIdx.x * blockDim.x + threadIdx.x;
    if (idx >= XEL) return;
    int x = idx & 63;
    int y = (idx >> 6) & 63;
    int ci = (idx >> 12) & 511;
    int b = idx >> 21;
    const float* p = xin + (size_t)(b * C_ + ci) * (HI * WI);
    g_xup[idx] = bilerp32(p, y, x) * g_s1[b * C_ + ci];
}

// ---------------- 3x3 conv, shared weights across batch ---------------------
// block: 64 co x (16x16) pixels, 256 threads, per-thread 8co x 8px
__global__ void __launch_bounds__(256, 2)
k_conv3x3(int pass,
          const float* __restrict__ noise,
          const float* __restrict__ Bvec,
          float* __restrict__ dout)
{
    const float* in = pass ? g_y1  : g_xup;
    const float* wt = pass ? g_w2t : g_w1t;
    const float* dm = pass ? g_d2  : g_d1;
    float* out      = pass ? dout  : g_y1;

    int b = blockIdx.y;
    int cb = blockIdx.x >> 4;          // 0..7  (co block)
    int tile = blockIdx.x & 15;
    int ty0 = (tile >> 2) * 16, tx0 = (tile & 3) * 16;

    __shared__ float s_in[4][18 * 18];
    __shared__ float s_w[4][9][64];

    int tid = threadIdx.x;
    int tco = tid & 7;                 // 8 co groups
    int tpx = tid >> 3;                // 32 pixel groups
    int r  = tpx >> 1;                 // row in tile 0..15
    int c0 = (tpx & 1) * 8;            // col start

    float acc[8][8];
    #pragma unroll
    for (int j = 0; j < 8; j++)
        #pragma unroll
        for (int p = 0; p < 8; p++) acc[j][p] = 0.f;

    int co_base = cb * 64;
    const float* inB = in + (size_t)b * C_ * PIX;

    for (int ci0 = 0; ci0 < C_; ci0 += 4) {
        __syncthreads();
        // input tile with halo: 4 x 18 x 18
        for (int i = tid; i < 4 * 324; i += 256) {
            int cc = i / 324; int rem = i - cc * 324;
            int ly = rem / 18, lx = rem - ly * 18;
            int gy = ty0 - 1 + ly, gx = tx0 - 1 + lx;
            float v = 0.f;
            if (gy >= 0 && gy < 64 && gx >= 0 && gx < 64)
                v = inB[(ci0 + cc) * PIX + gy * 64 + gx];
            s_in[cc][ly * 18 + lx] = v;
        }
        // weights: 4 ci x 9 taps x 64 co (coalesced from transposed layout)
        for (int i = tid; i < 4 * 576; i += 256) {
            int cc = i / 576; int rem = i - cc * 576;
            int tap = rem >> 6; int col = rem & 63;
            s_w[cc][tap][col] = wt[((ci0 + cc) * 9 + tap) * C_ + co_base + col];
        }
        __syncthreads();

        #pragma unroll
        for (int cc = 0; cc < 4; cc++) {
            float rin[3][10];
            #pragma unroll
            for (int dy = 0; dy < 3; dy++)
                #pragma unroll
                for (int i = 0; i < 10; i++)
                    rin[dy][i] = s_in[cc][(r + dy) * 18 + c0 + i];
            #pragma unroll
            for (int j = 0; j < 8; j++) {
                const float* wp = &s_w[cc][0][tco * 8 + j];
                float w0 = wp[0],   w1 = wp[64],  w2 = wp[128];
                float w3 = wp[192], w4 = wp[256], w5 = wp[320];
                float w6 = wp[384], w7 = wp[448], w8 = wp[512];
                #pragma unroll
                for (int p = 0; p < 8; p++) {
                    float a = acc[j][p];
                    a = fmaf(w0, rin[0][p    ], a);
                    a = fmaf(w1, rin[0][p + 1], a);
                    a = fmaf(w2, rin[0][p + 2], a);
                    a = fmaf(w3, rin[1][p    ], a);
                    a = fmaf(w4, rin[1][p + 1], a);
                    a = fmaf(w5, rin[1][p + 2], a);
                    a = fmaf(w6, rin[2][p    ], a);
                    a = fmaf(w7, rin[2][p + 1], a);
                    a = fmaf(w8, rin[2][p + 2], a);
                    acc[j][p] = a;
                }
            }
        }
    }

    // epilogue: demod + noise + leaky (+ next style for pass 0)
    int y = ty0 + r;
    float nz[8];
    #pragma unroll
    for (int p = 0; p < 8; p++) nz[p] = noise[b * PIX + y * 64 + tx0 + c0 + p];

    #pragma unroll
    for (int j = 0; j < 8; j++) {
        int co = co_base + tco * 8 + j;
        float d  = dm[b * C_ + co];
        float bb = Bvec[co];
        float ps = pass ? 1.f : g_s2[b * C_ + co];
        float* orow = out + ((size_t)(b * C_ + co) * PIX) + y * 64 + tx0 + c0;
        #pragma unroll
        for (int p = 0; p < 8; p++) {
            float v = d * acc[j][p] + bb * nz[p];
            v = (v >= 0.f) ? v : SLOPE * v;
            orow[p] = v * ps;
        }
    }
}

// ---------------- toRGB 1x1 + rgb upsample + add ----------------------------
__global__ void k_final(const float* __restrict__ y2,      // d_out x region
                        const float* __restrict__ rgb_in,
                        const float* __restrict__ noise3,
                        const float* __restrict__ B3,
                        float* __restrict__ out_rgb)
{
    int b = blockIdx.y;
    int p = blockIdx.x * 256 + threadIdx.x;   // 0..4095
    __shared__ float s_m3[3 * C_];
    for (int i = threadIdx.x; i < 3 * C_; i += 256) s_m3[i] = g_m3[b * 3 * C_ + i];
    __syncthreads();

    int y = p >> 6, x = p & 63;
    const float* yb = y2 + (size_t)b * C_ * PIX + p;
    float a0 = 0.f, a1 = 0.f, a2 = 0.f;
    #pragma unroll 8
    for (int ci = 0; ci < C_; ci++) {
        float v = yb[(size_t)ci * PIX];
        a0 = fmaf(s_m3[ci], v, a0);
        a1 = fmaf(s_m3[C_ + ci], v, a1);
        a2 = fmaf(s_m3[2 * C_ + ci], v, a2);
    }
    float nz = noise3[b * PIX + p];
    float a[3] = {a0, a1, a2};
    #pragma unroll
    for (int j = 0; j < 3; j++) {
        float v = a[j] + B3[j] * nz;
        v = (v >= 0.f) ? v : SLOPE * v;
        const float* rp = rgb_in + (size_t)(b * 3 + j) * (HI * WI);
        out_rgb[(size_t)(b * 3 + j) * PIX + p] = bilerp32(rp, y, x) + v;
    }
}

// ---------------- launcher ---------------------------------------------------
extern "C" void kernel_launch(void* const* d_in, const int* in_sizes, int n_in,
                              void* d_out, int out_size)
{
    const float* x    = (const float*)d_in[0];
    const float* rgb  = (const float*)d_in[1];
    const float* w    = (const float*)d_in[2];
    const float* n1   = (const float*)d_in[3];
    const float* n2   = (const float*)d_in[4];
    const float* n3   = (const float*)d_in[5];
    const float* wt1  = (const float*)d_in[6];
    const float* A1w  = (const float*)d_in[7];
    const float* A1b  = (const float*)d_in[8];
    const float* B1   = (const float*)d_in[9];
    const float* wt2  = (const float*)d_in[10];
    const float* A2w  = (const float*)d_in[11];
    const float* A2b  = (const float*)d_in[12];
    const float* B2   = (const float*)d_in[13];
    const float* wt3  = (const float*)d_in[14];
    const float* A3w  = (const float*)d_in[15];
    const float* A3b  = (const float*)d_in[16];
    const float* B3   = (const float*)d_in[17];
    float* out = (float*)d_out;

    k_styles<<<(3 * B_ * C_ + 7) / 8, 256>>>(w, A1w, A1b, A2w, A2b, A3w, A3b);
    k_wprep <<<(2 * C_ * C_ + 255) / 256, 256>>>(wt1, wt2);
    k_demod <<<(2 * B_ * C_ + 7) / 8, 256>>>();
    k_m3    <<<B_ * 3, 128>>>(wt3);
    k_upx   <<<XEL / 256, 256>>>(x);
    k_conv3x3<<<dim3(128, B_), 256>>>(0, n1, B1, out);
    k_conv3x3<<<dim3(128, B_), 256>>>(1, n2, B2, out);
    k_final <<<dim3(PIX / 256, B_), 256>>>(out, rgb, n3, B3, out + (size_t)XEL);
}

// round 5
// speedup vs baseline: 3.1364x; 3.1364x over previous
#include <cuda_runtime.h>
#include <cuda_bf16.h>
#include <cstdint>

// ============================================================================
// BlockG via mma.sync bf16-split implicit GEMM (sm_100-safe: no tcgen05).
//   conv = scale-input-by-style, shared-weight conv, scale-output-by-demod.
//   3x3 conv = 9 row-offset taps into one padded-NHWC smem region.
//   fp32 v = bf16 hi + bf16 lo;  A*B ~= Ah*Bh + Ah*Bl + Al*Bh (3 MMA terms).
// Output: d_out[0:8*512*64*64) = x (fp32 NCHW), then [..:+8*3*64*64) = rgb.
// ============================================================================

#define B_ 8
#define C_ 512
#define PIX 4096
#define XEL (B_*C_*PIX)
#define QW 66
#define SLAB 4368
#define NT 128
#define NTILES 33
#define REGROWS 262
#define EPSV 1e-8f
#define SLOPE 0.2f

#define OFF_XH 0
#define OFF_XL 33792
#define OFF_WH 67584
#define OFF_WL 83968
#define SMEM_CONV 100352

// ---------------- device scratch ----------------
__device__ __nv_bfloat16 g_x1h[B_*SLAB*C_], g_x1l[B_*SLAB*C_];
__device__ __nv_bfloat16 g_x2h[B_*SLAB*C_], g_x2l[B_*SLAB*C_];
__device__ __nv_bfloat16 g_wb1h[9*C_*C_], g_wb1l[9*C_*C_];   // [tap][co][ci]
__device__ __nv_bfloat16 g_wb2h[9*C_*C_], g_wb2l[9*C_*C_];
__device__ float g_w2s1[C_*C_], g_w2s2[C_*C_];
__device__ float g_s1[B_*C_], g_s2[B_*C_], g_s3[B_*C_];
__device__ float g_d1[B_*C_], g_d2[B_*C_];
__device__ float g_m3[B_*3*C_];

// ---------------- helpers ----------------
__device__ __forceinline__ uint32_t smem_u32(const void* p) {
    uint32_t a;
    asm("{ .reg .u64 t; cvta.to.shared.u64 t, %1; cvt.u32.u64 %0, t; }" : "=r"(a) : "l"(p));
    return a;
}
__device__ __forceinline__ uint32_t swz(uint32_t o) { return o ^ ((o >> 3) & 0x70); }

__device__ __forceinline__ void ldsm4(uint32_t* r, uint32_t addr) {
    asm volatile("ldmatrix.sync.aligned.m8n8.x4.shared.b16 {%0,%1,%2,%3}, [%4];"
        : "=r"(r[0]), "=r"(r[1]), "=r"(r[2]), "=r"(r[3]) : "r"(addr));
}
__device__ __forceinline__ void mma16816(float* c, const uint32_t* a, uint32_t b0, uint32_t b1) {
    asm volatile("mma.sync.aligned.m16n8k16.row.col.f32.bf16.bf16.f32 "
        "{%0,%1,%2,%3}, {%4,%5,%6,%7}, {%8,%9}, {%0,%1,%2,%3};"
        : "+f"(c[0]), "+f"(c[1]), "+f"(c[2]), "+f"(c[3])
        : "r"(a[0]), "r"(a[1]), "r"(a[2]), "r"(a[3]), "r"(b0), "r"(b1));
}

// ---------------- styles ----------------
__global__ void k_styles(const float* __restrict__ w,
                         const float* __restrict__ A1, const float* __restrict__ b1,
                         const float* __restrict__ A2, const float* __restrict__ b2,
                         const float* __restrict__ A3, const float* __restrict__ b3)
{
    int gw = (blockIdx.x * blockDim.x + threadIdx.x) >> 5;
    int lane = threadIdx.x & 31;
    if (gw >= 3 * B_ * C_) return;
    int m = gw / (B_ * C_);
    int r = gw - m * (B_ * C_);
    int b = r >> 9, i = r & 511;
    const float* A  = (m == 0) ? A1 : (m == 1) ? A2 : A3;
    const float* bs = (m == 0) ? b1 : (m == 1) ? b2 : b3;
    float acc = 0.f;
    const float* wb = w + b * C_;
    const float* Ai = A + i * C_;
    for (int k = lane; k < C_; k += 32) acc += wb[k] * Ai[k];
    #pragma unroll
    for (int o = 16; o > 0; o >>= 1) acc += __shfl_xor_sync(0xffffffffu, acc, o);
    if (lane == 0) {
        float* out = (m == 0) ? g_s1 : (m == 1) ? g_s2 : g_s3;
        out[b * C_ + i] = acc + bs[i];
    }
}

// ---------------- weight prep: sumsq + bf16-split transpose -----------------
__global__ void k_wprep(const float* __restrict__ w1, const float* __restrict__ w2)
{
    int idx = blockIdx.x * blockDim.x + threadIdx.x;
    if (idx >= 2 * C_ * C_) return;
    int m = idx >> 18;
    int r = idx & (C_ * C_ - 1);
    int co = r >> 9, ci = r & 511;
    const float* w = m ? w2 : w1;
    float* w2s = m ? g_w2s2 : g_w2s1;
    __nv_bfloat16* wh = m ? g_wb2h : g_wb1h;
    __nv_bfloat16* wl = m ? g_wb2l : g_wb1l;
    const float* src = w + (size_t)(co * C_ + ci) * 9;
    float ss = 0.f;
    #pragma unroll
    for (int t = 0; t < 9; t++) {
        float v = src[t];
        ss += v * v;
        __nv_bfloat16 h = __float2bfloat16(v);
        size_t o = ((size_t)t * C_ + co) * C_ + ci;
        wh[o] = h;
        wl[o] = __float2bfloat16(v - __bfloat162float(h));
    }
    w2s[co * C_ + ci] = ss;
}

// ---------------- demod ----------------
__global__ void k_demod()
{
    int gw = (blockIdx.x * blockDim.x + threadIdx.x) >> 5;
    int lane = threadIdx.x & 31;
    if (gw >= 2 * B_ * C_) return;
    int m = gw >> 12;
    int r = gw & 4095;
    int b = r >> 9, co = r & 511;
    const float* w2s = m ? g_w2s2 : g_w2s1;
    const float* s   = m ? g_s2   : g_s1;
    float acc = 0.f;
    const float* wr = w2s + co * C_;
    const float* sr = s + b * C_;
    for (int ci = lane; ci < C_; ci += 32) { float sv = sr[ci]; acc += wr[ci] * sv * sv; }
    #pragma unroll
    for (int o = 16; o > 0; o >>= 1) acc += __shfl_xor_sync(0xffffffffu, acc, o);
    if (lane == 0) {
        float* d = m ? g_d2 : g_d1;
        d[b * C_ + co] = rsqrtf(acc + EPSV);
    }
}

// ---------------- toRGB modulation ----------------
__global__ void k_m3(const float* __restrict__ w3)
{
    int b = blockIdx.x / 3, j = blockIdx.x % 3;
    __shared__ float red[128];
    __shared__ float d3s;
    int tid = threadIdx.x;
    float acc = 0.f;
    for (int ci = tid; ci < C_; ci += 128) {
        float t = w3[j * C_ + ci] * g_s3[b * C_ + ci];
        acc += t * t;
    }
    red[tid] = acc; __syncthreads();
    for (int o = 64; o > 0; o >>= 1) { if (tid < o) red[tid] += red[tid + o]; __syncthreads(); }
    if (tid == 0) d3s = rsqrtf(red[0] + EPSV);
    __syncthreads();
    float d3 = d3s;
    for (int ci = tid; ci < C_; ci += 128)
        g_m3[(b * 3 + j) * C_ + ci] = w3[j * C_ + ci] * g_s3[b * C_ + ci] * d3;
}

// ---------------- zero borders + tail of padded NHWC buffers ----------------
__global__ void k_zero()
{
    int i = blockIdx.x % 272;
    int b = blockIdx.x / 272;
    int q;
    if (i < 66)       q = i;                          // top row
    else if (i < 132) q = 4290 + (i - 66);            // bottom row
    else if (i < 196) q = (i - 132 + 1) * QW;         // left col
    else if (i < 260) q = (i - 196 + 1) * QW + 65;    // right col
    else              q = 4356 + (i - 260);           // tail rows
    size_t o = ((size_t)b * SLAB + q) * C_ / 2 + threadIdx.x;
    ((uint32_t*)g_x1h)[o] = 0u; ((uint32_t*)g_x1l)[o] = 0u;
    ((uint32_t*)g_x2h)[o] = 0u; ((uint32_t*)g_x2l)[o] = 0u;
}

// ---------------- upsample x2 + style, write split bf16 NHWC ----------------
__global__ void k_up(const float* __restrict__ xin)
{
    int y = blockIdx.x, cc = blockIdx.y, b = blockIdx.z;
    int ci0 = cc * 64;
    __shared__ float sin_[2][64][33];
    __shared__ float ss1[64];
    const float F = 31.0f / 63.0f;
    float cy = (float)y * F;
    int iy0 = (int)cy;
    float ty = cy - (float)iy0;
    int iy1 = min(iy0 + 1, 31);
    int tid = threadIdx.x;
    for (int i = tid; i < 2 * 64 * 32; i += 256) {
        int rr = i >> 11, rem = i & 2047, c = rem >> 5, xx = rem & 31;
        int iy = rr ? iy1 : iy0;
        sin_[rr][c][xx] = xin[((size_t)(b * C_ + ci0 + c) * 32 + iy) * 32 + xx];
    }
    if (tid < 64) ss1[tid] = g_s1[b * C_ + ci0 + tid];
    __syncthreads();
    #pragma unroll
    for (int j = 0; j < 16; j++) {
        int x = (tid >> 6) + j * 4;
        int c = tid & 63;
        float cx = (float)x * F;
        int ix0 = (int)cx;
        float tx = cx - (float)ix0;
        int ix1 = min(ix0 + 1, 31);
        float a0 = sin_[0][c][ix0] * (1.f - ty) + sin_[1][c][ix0] * ty;
        float a1 = sin_[0][c][ix1] * (1.f - ty) + sin_[1][c][ix1] * ty;
        float v = (a0 * (1.f - tx) + a1 * tx) * ss1[c];
        __nv_bfloat16 h = __float2bfloat16(v);
        size_t o = ((size_t)b * SLAB + (y + 1) * QW + (x + 1)) * C_ + ci0 + c;
        g_x1h[o] = h;
        g_x1l[o] = __float2bfloat16(v - __bfloat162float(h));
    }
}

// ---------------- mma.sync conv 3x3 ----------------
// CTA: 128 co x 128 px, 4 warps each m64 x n64.
__global__ void __launch_bounds__(128, 2)
k_conv(int pass, const float* __restrict__ noise, const float* __restrict__ Bvec,
       float* __restrict__ outx)
{
    extern __shared__ __align__(1024) char dsm[];

    const __nv_bfloat16* xh  = pass ? g_x2h  : g_x1h;
    const __nv_bfloat16* xl  = pass ? g_x2l  : g_x1l;
    const __nv_bfloat16* wbh = pass ? g_wb2h : g_wb1h;
    const __nv_bfloat16* wbl = pass ? g_wb2l : g_wb1l;
    const float* dm = pass ? g_d2 : g_d1;

    int tid = threadIdx.x;
    int wid = tid >> 5, lane = tid & 31;
    int wm = wid & 1, wn = wid >> 1;          // warp pos: m (co) / n (px)
    int b = blockIdx.z, cb = blockIdx.y, ntile = blockIdx.x;
    int P0 = ntile * NT;
    int co_base = cb * 128;

    uint32_t sb = smem_u32(dsm);
    uint32_t sXH = sb + OFF_XH, sXL = sb + OFF_XL;
    uint32_t sWH = sb + OFF_WH, sWL = sb + OFF_WL;

    // ldmatrix lane geometry
    int a_row = ((lane >> 3) & 1) * 8 + (lane & 7);
    int a_kb  = (lane >> 4) * 16;
    int b_n   = (lane >> 4) * 8 + (lane & 7);
    int b_kb  = ((lane >> 3) & 1) * 16;

    float acc[4][8][4];
    #pragma unroll
    for (int mi = 0; mi < 4; mi++)
        #pragma unroll
        for (int f = 0; f < 8; f++)
            #pragma unroll
            for (int r = 0; r < 4; r++) acc[mi][f][r] = 0.f;

    // A row byte offsets (weights, k-add applied per step)
    uint32_t rowA[4];
    #pragma unroll
    for (int mi = 0; mi < 4; mi++)
        rowA[mi] = (uint32_t)((wm * 64 + mi * 16 + a_row) * 128 + a_kb);

    const size_t xgbase = ((size_t)b * SLAB + P0) * C_;

    for (int ci0 = 0; ci0 < C_; ci0 += 64) {
        __syncthreads();
        // stage input region: 262 rows x 64 ci (hi + lo)
        for (int i = tid; i < REGROWS * 8; i += 128) {
            int r = i >> 3, j = i & 7;
            size_t g = xgbase + (size_t)r * C_ + ci0 + j * 8;
            uint32_t so = swz((uint32_t)(r * 128 + j * 16));
            *(uint4*)(dsm + OFF_XH + so) = *(const uint4*)(xh + g);
            *(uint4*)(dsm + OFF_XL + so) = *(const uint4*)(xl + g);
        }
        for (int tap = 0; tap < 9; tap++) {
            __syncthreads();
            // stage weights for this tap: 128 co x 64 ci (hi + lo)
            {
                const size_t wgbase = ((size_t)(tap * C_ + co_base)) * C_ + ci0;
                for (int i = tid; i < 128 * 8; i += 128) {
                    int r = i >> 3, j = i & 7;
                    size_t g = wgbase + (size_t)r * C_ + j * 8;
                    uint32_t so = swz((uint32_t)(r * 128 + j * 16));
                    *(uint4*)(dsm + OFF_WH + so) = *(const uint4*)(wbh + g);
                    *(uint4*)(dsm + OFF_WL + so) = *(const uint4*)(wbl + g);
                }
            }
            __syncthreads();

            int toff = (tap / 3) * QW + (tap % 3);
            uint32_t rowB[4];
            #pragma unroll
            for (int nj = 0; nj < 4; nj++)
                rowB[nj] = (uint32_t)((wn * 64 + nj * 16 + b_n + toff) * 128 + b_kb);

            #pragma unroll
            for (int ks = 0; ks < 4; ks++) {
                uint32_t kadd = ks * 32;
                uint32_t Ah[4][4], Al[4][4], Bh[4][4], Bl[4][4];
                #pragma unroll
                for (int mi = 0; mi < 4; mi++) {
                    uint32_t ro = swz(rowA[mi] + kadd);
                    ldsm4(Ah[mi], sWH + ro);
                    ldsm4(Al[mi], sWL + ro);
                }
                #pragma unroll
                for (int nj = 0; nj < 4; nj++) {
                    uint32_t ro = swz(rowB[nj] + kadd);
                    ldsm4(Bh[nj], sXH + ro);
                    ldsm4(Bl[nj], sXL + ro);
                }
                #pragma unroll
                for (int mi = 0; mi < 4; mi++) {
                    #pragma unroll
                    for (int f = 0; f < 8; f++) {
                        int bi = f >> 1, br = (f & 1) * 2;
                        mma16816(acc[mi][f], Ah[mi], Bh[bi][br], Bh[bi][br + 1]);
                        mma16816(acc[mi][f], Ah[mi], Bl[bi][br], Bl[bi][br + 1]);
                        mma16816(acc[mi][f], Al[mi], Bh[bi][br], Bh[bi][br + 1]);
                    }
                }
            }
        }
    }

    // ---------------- epilogue ----------------
    int g = lane >> 2, c2 = (lane & 3) * 2;
    #pragma unroll
    for (int mi = 0; mi < 4; mi++) {
        #pragma unroll
        for (int rh = 0; rh < 2; rh++) {
            int co_g = co_base + wm * 64 + mi * 16 + g + rh * 8;
            float d   = dm[b * C_ + co_g];
            float bb  = Bvec[co_g];
            float s2v = pass ? 1.f : g_s2[b * C_ + co_g];
            #pragma unroll
            for (int f = 0; f < 8; f++) {
                #pragma unroll
                for (int rl = 0; rl < 2; rl++) {
                    int col = wn * 64 + f * 8 + c2 + rl;
                    int p = P0 + col;
                    int y = p / QW;
                    int x = p - y * QW;
                    if (x < 64) {
                        float v = d * acc[mi][f][rh * 2 + rl] + bb * noise[b * PIX + y * 64 + x];
                        v = (v >= 0.f) ? v : SLOPE * v;
                        if (pass == 0) {
                            v *= s2v;
                            __nv_bfloat16 h = __float2bfloat16(v);
                            size_t o = ((size_t)b * SLAB + (y + 1) * QW + (x + 1)) * C_ + co_g;
                            g_x2h[o] = h;
                            g_x2l[o] = __float2bfloat16(v - __bfloat162float(h));
                        } else {
                            outx[((size_t)(b * C_ + co_g)) * PIX + y * 64 + x] = v;
                        }
                    }
                }
            }
        }
    }
}

// ---------------- toRGB 1x1 + rgb upsample + add ----------------------------
__device__ __forceinline__ float bilerp32(const float* __restrict__ p, int y, int x)
{
    const float F = 31.0f / 63.0f;
    float cy = (float)y * F, cx = (float)x * F;
    int iy0 = (int)cy, ix0 = (int)cx;
    float ty = cy - (float)iy0, tx = cx - (float)ix0;
    int iy1 = min(iy0 + 1, 31), ix1 = min(ix0 + 1, 31);
    float v00 = p[iy0 * 32 + ix0], v01 = p[iy0 * 32 + ix1];
    float v10 = p[iy1 * 32 + ix0], v11 = p[iy1 * 32 + ix1];
    float a = v00 * (1.f - ty) + v10 * ty;
    float c = v01 * (1.f - ty) + v11 * ty;
    return a * (1.f - tx) + c * tx;
}

__global__ void k_final(const float* __restrict__ y2,
                        const float* __restrict__ rgb_in,
                        const float* __restrict__ noise3,
                        const float* __restrict__ B3,
                        float* __restrict__ out_rgb)
{
    int b = blockIdx.y;
    int p = blockIdx.x * 256 + threadIdx.x;
    __shared__ float s_m3[3 * C_];
    for (int i = threadIdx.x; i < 3 * C_; i += 256) s_m3[i] = g_m3[b * 3 * C_ + i];
    __syncthreads();

    int y = p >> 6, x = p & 63;
    const float* yb = y2 + (size_t)b * C_ * PIX + p;
    float a0 = 0.f, a1 = 0.f, a2 = 0.f;
    #pragma unroll 8
    for (int ci = 0; ci < C_; ci++) {
        float v = yb[(size_t)ci * PIX];
        a0 = fmaf(s_m3[ci], v, a0);
        a1 = fmaf(s_m3[C_ + ci], v, a1);
        a2 = fmaf(s_m3[2 * C_ + ci], v, a2);
    }
    float nz = noise3[b * PIX + p];
    float a[3] = {a0, a1, a2};
    #pragma unroll
    for (int j = 0; j < 3; j++) {
        float v = a[j] + B3[j] * nz;
        v = (v >= 0.f) ? v : SLOPE * v;
        const float* rp = rgb_in + (size_t)(b * 3 + j) * 1024;
        out_rgb[(size_t)(b * 3 + j) * PIX + p] = bilerp32(rp, y, x) + v;
    }
}

// ---------------- launcher ---------------------------------------------------
extern "C" void kernel_launch(void* const* d_in, const int* in_sizes, int n_in,
                              void* d_out, int out_size)
{
    const float* x    = (const float*)d_in[0];
    const float* rgb  = (const float*)d_in[1];
    const float* w    = (const float*)d_in[2];
    const float* n1   = (const float*)d_in[3];
    const float* n2   = (const float*)d_in[4];
    const float* n3   = (const float*)d_in[5];
    const float* wt1  = (const float*)d_in[6];
    const float* A1w  = (const float*)d_in[7];
    const float* A1b  = (const float*)d_in[8];
    const float* B1   = (const float*)d_in[9];
    const float* wt2  = (const float*)d_in[10];
    const float* A2w  = (const float*)d_in[11];
    const float* A2b  = (const float*)d_in[12];
    const float* B2   = (const float*)d_in[13];
    const float* wt3  = (const float*)d_in[14];
    const float* A3w  = (const float*)d_in[15];
    const float* A3b  = (const float*)d_in[16];
    const float* B3   = (const float*)d_in[17];
    float* out = (float*)d_out;

    static int smem_set = 0;
    if (!smem_set) {
        cudaFuncSetAttribute(k_conv, cudaFuncAttributeMaxDynamicSharedMemorySize, SMEM_CONV);
        smem_set = 1;
    }

    k_styles<<<(3 * B_ * C_ + 7) / 8, 256>>>(w, A1w, A1b, A2w, A2b, A3w, A3b);
    k_wprep <<<(2 * C_ * C_ + 255) / 256, 256>>>(wt1, wt2);
    k_demod <<<(2 * B_ * C_ + 7) / 8, 256>>>();
    k_m3    <<<B_ * 3, 128>>>(wt3);
    k_zero  <<<B_ * 272, 256>>>();
    k_up    <<<dim3(64, 8, B_), 256>>>(x);
    k_conv  <<<dim3(NTILES, 4, B_), 128, SMEM_CONV>>>(0, n1, B1, out);
    k_conv  <<<dim3(NTILES, 4, B_), 128, SMEM_CONV>>>(1, n2, B2, out);
    k_final <<<dim3(PIX / 256, B_), 256>>>(out, rgb, n3, B3, out + (size_t)XEL);
}

// round 8
// speedup vs baseline: 3.2451x; 1.0347x over previous
#include <cuda_runtime.h>
#include <cuda_bf16.h>
#include <cstdint>

// ============================================================================
// BlockG via mma.sync bf16-split implicit GEMM, cp.async-pipelined.
//   conv = scale-input-by-style, shared-weight conv, scale-output-by-demod.
//   3x3 conv = 9 row-offset taps into one padded-NHWC smem region.
//   fp32 v = bf16 hi + bf16 lo;  A*B ~= Ah*Bh + Ah*Bl + Al*Bh (3 MMA terms).
// Output: d_out[0:8*512*64*64) = x (fp32 NCHW), then [..:+8*3*64*64) = rgb.
// ============================================================================

#define B_ 8
#define C_ 512
#define PIX 4096
#define XEL (B_*C_*PIX)
#define QW 66
#define SLAB 4496
#define NT 256
#define NTILES 17
#define REGROWS 392
#define EPSV 1e-8f
#define SLOPE 0.2f

// dynamic smem layout (bytes; all 1024-aligned)
#define OFF_XH 0
#define OFF_XL 50176
#define OFF_W  100352
#define WBUF   32768
#define SMEM_CONV 165888

// ---------------- device scratch ----------------
__device__ __nv_bfloat16 g_x1h[B_*SLAB*C_], g_x1l[B_*SLAB*C_];
__device__ __nv_bfloat16 g_x2h[B_*SLAB*C_], g_x2l[B_*SLAB*C_];
__device__ __nv_bfloat16 g_wb1h[9*C_*C_], g_wb1l[9*C_*C_];   // [tap][co][ci]
__device__ __nv_bfloat16 g_wb2h[9*C_*C_], g_wb2l[9*C_*C_];
__device__ float g_w2s1[C_*C_], g_w2s2[C_*C_];
__device__ float g_s1[B_*C_], g_s2[B_*C_], g_s3[B_*C_];
__device__ float g_d1[B_*C_], g_d2[B_*C_];
__device__ float g_m3[B_*3*C_];

// ---------------- helpers ----------------
__device__ __forceinline__ uint32_t smem_u32(const void* p) {
    uint32_t a;
    asm("{ .reg .u64 t; cvta.to.shared.u64 t, %1; cvt.u32.u64 %0, t; }" : "=r"(a) : "l"(p));
    return a;
}
__device__ __forceinline__ uint32_t swz(uint32_t o) { return o ^ ((o >> 3) & 0x70); }

__device__ __forceinline__ void cpa16(uint32_t dst, const void* gsrc) {
    asm volatile("cp.async.cg.shared.global [%0], [%1], 16;"
        :: "r"(dst), "l"(__cvta_generic_to_global(gsrc)) : "memory");
}
__device__ __forceinline__ void cpa_commit() {
    asm volatile("cp.async.commit_group;" ::: "memory");
}
__device__ __forceinline__ void cpa_wait0() {
    asm volatile("cp.async.wait_group 0;" ::: "memory");
}

__device__ __forceinline__ void ldsm4(uint32_t* r, uint32_t addr) {
    asm volatile("ldmatrix.sync.aligned.m8n8.x4.shared.b16 {%0,%1,%2,%3}, [%4];"
        : "=r"(r[0]), "=r"(r[1]), "=r"(r[2]), "=r"(r[3]) : "r"(addr));
}
__device__ __forceinline__ void mma16816(float* c, const uint32_t* a, uint32_t b0, uint32_t b1) {
    asm volatile("mma.sync.aligned.m16n8k16.row.col.f32.bf16.bf16.f32 "
        "{%0,%1,%2,%3}, {%4,%5,%6,%7}, {%8,%9}, {%0,%1,%2,%3};"
        : "+f"(c[0]), "+f"(c[1]), "+f"(c[2]), "+f"(c[3])
        : "r"(a[0]), "r"(a[1]), "r"(a[2]), "r"(a[3]), "r"(b0), "r"(b1));
}

// ---------------- styles ----------------
__global__ void k_styles(const float* __restrict__ w,
                         const float* __restrict__ A1, const float* __restrict__ b1,
                         const float* __restrict__ A2, const float* __restrict__ b2,
                         const float* __restrict__ A3, const float* __restrict__ b3)
{
    int gw = (blockIdx.x * blockDim.x + threadIdx.x) >> 5;
    int lane = threadIdx.x & 31;
    if (gw >= 3 * B_ * C_) return;
    int m = gw / (B_ * C_);
    int r = gw - m * (B_ * C_);
    int b = r >> 9, i = r & 511;
    const float* A  = (m == 0) ? A1 : (m == 1) ? A2 : A3;
    const float* bs = (m == 0) ? b1 : (m == 1) ? b2 : b3;
    float acc = 0.f;
    const float* wb = w + b * C_;
    const float* Ai = A + i * C_;
    for (int k = lane; k < C_; k += 32) acc += wb[k] * Ai[k];
    #pragma unroll
    for (int o = 16; o > 0; o >>= 1) acc += __shfl_xor_sync(0xffffffffu, acc, o);
    if (lane == 0) {
        float* out = (m == 0) ? g_s1 : (m == 1) ? g_s2 : g_s3;
        out[b * C_ + i] = acc + bs[i];
    }
}

// ---------------- weight prep: sumsq + bf16-split transpose -----------------
__global__ void k_wprep(const float* __restrict__ w1, const float* __restrict__ w2)
{
    int idx = blockIdx.x * blockDim.x + threadIdx.x;
    if (idx >= 2 * C_ * C_) return;
    int m = idx >> 18;
    int r = idx & (C_ * C_ - 1);
    int co = r >> 9, ci = r & 511;
    const float* w = m ? w2 : w1;
    float* w2s = m ? g_w2s2 : g_w2s1;
    __nv_bfloat16* wh = m ? g_wb2h : g_wb1h;
    __nv_bfloat16* wl = m ? g_wb2l : g_wb1l;
    const float* src = w + (size_t)(co * C_ + ci) * 9;
    float ss = 0.f;
    #pragma unroll
    for (int t = 0; t < 9; t++) {
        float v = src[t];
        ss += v * v;
        __nv_bfloat16 h = __float2bfloat16(v);
        size_t o = ((size_t)t * C_ + co) * C_ + ci;
        wh[o] = h;
        wl[o] = __float2bfloat16(v - __bfloat162float(h));
    }
    w2s[co * C_ + ci] = ss;
}

// ---------------- demod ----------------
__global__ void k_demod()
{
    int gw = (blockIdx.x * blockDim.x + threadIdx.x) >> 5;
    int lane = threadIdx.x & 31;
    if (gw >= 2 * B_ * C_) return;
    int m = gw >> 12;
    int r = gw & 4095;
    int b = r >> 9, co = r & 511;
    const float* w2s = m ? g_w2s2 : g_w2s1;
    const float* s   = m ? g_s2   : g_s1;
    float acc = 0.f;
    const float* wr = w2s + co * C_;
    const float* sr = s + b * C_;
    for (int ci = lane; ci < C_; ci += 32) { float sv = sr[ci]; acc += wr[ci] * sv * sv; }
    #pragma unroll
    for (int o = 16; o > 0; o >>= 1) acc += __shfl_xor_sync(0xffffffffu, acc, o);
    if (lane == 0) {
        float* d = m ? g_d2 : g_d1;
        d[b * C_ + co] = rsqrtf(acc + EPSV);
    }
}

// ---------------- toRGB modulation ----------------
__global__ void k_m3(const float* __restrict__ w3)
{
    int b = blockIdx.x / 3, j = blockIdx.x % 3;
    __shared__ float red[128];
    __shared__ float d3s;
    int tid = threadIdx.x;
    float acc = 0.f;
    for (int ci = tid; ci < C_; ci += 128) {
        float t = w3[j * C_ + ci] * g_s3[b * C_ + ci];
        acc += t * t;
    }
    red[tid] = acc; __syncthreads();
    for (int o = 64; o > 0; o >>= 1) { if (tid < o) red[tid] += red[tid + o]; __syncthreads(); }
    if (tid == 0) d3s = rsqrtf(red[0] + EPSV);
    __syncthreads();
    float d3 = d3s;
    for (int ci = tid; ci < C_; ci += 128)
        g_m3[(b * 3 + j) * C_ + ci] = w3[j * C_ + ci] * g_s3[b * C_ + ci] * d3;
}

// ---------------- zero borders + tail of padded NHWC buffers ----------------
// rows to zero per batch: top 66, bottom 66, left 64, right 64, tail 140 = 400
__global__ void k_zero()
{
    int i = blockIdx.x % 400;
    int b = blockIdx.x / 400;
    int q;
    if (i < 66)       q = i;                          // top row (y'=0)
    else if (i < 132) q = 4290 + (i - 66);            // bottom row (y'=65)
    else if (i < 196) q = (i - 132 + 1) * QW;         // left col
    else if (i < 260) q = (i - 196 + 1) * QW + 65;    // right col
    else              q = 4356 + (i - 260);           // tail rows [4356,4496)
    size_t o = ((size_t)b * SLAB + q) * C_ / 2 + threadIdx.x;
    ((uint32_t*)g_x1h)[o] = 0u; ((uint32_t*)g_x1l)[o] = 0u;
    ((uint32_t*)g_x2h)[o] = 0u; ((uint32_t*)g_x2l)[o] = 0u;
}

// ---------------- upsample x2 + style, write split bf16 NHWC ----------------
__global__ void k_up(const float* __restrict__ xin)
{
    int y = blockIdx.x, cc = blockIdx.y, b = blockIdx.z;
    int ci0 = cc * 64;
    __shared__ float sin_[2][64][33];
    __shared__ float ss1[64];
    const float F = 31.0f / 63.0f;
    float cy = (float)y * F;
    int iy0 = (int)cy;
    float ty = cy - (float)iy0;
    int iy1 = min(iy0 + 1, 31);
    int tid = threadIdx.x;
    for (int i = tid; i < 2 * 64 * 32; i += 256) {
        int rr = i >> 11, rem = i & 2047, c = rem >> 5, xx = rem & 31;
        int iy = rr ? iy1 : iy0;
        sin_[rr][c][xx] = xin[((size_t)(b * C_ + ci0 + c) * 32 + iy) * 32 + xx];
    }
    if (tid < 64) ss1[tid] = g_s1[b * C_ + ci0 + tid];
    __syncthreads();
    #pragma unroll
    for (int j = 0; j < 16; j++) {
        int x = (tid >> 6) + j * 4;
        int c = tid & 63;
        float cx = (float)x * F;
        int ix0 = (int)cx;
        float tx = cx - (float)ix0;
        int ix1 = min(ix0 + 1, 31);
        float a0 = sin_[0][c][ix0] * (1.f - ty) + sin_[1][c][ix0] * ty;
        float a1 = sin_[0][c][ix1] * (1.f - ty) + sin_[1][c][ix1] * ty;
        float v = (a0 * (1.f - tx) + a1 * tx) * ss1[c];
        __nv_bfloat16 h = __float2bfloat16(v);
        size_t o = ((size_t)b * SLAB + (y + 1) * QW + (x + 1)) * C_ + ci0 + c;
        g_x1h[o] = h;
        g_x1l[o] = __float2bfloat16(v - __bfloat162float(h));
    }
}

// ---------------- mma.sync conv 3x3, cp.async pipelined ---------------------
// CTA: 128 co x 256 px, 8 warps (2m x 4n) each m64 x n64.
__global__ void __launch_bounds__(256)
k_conv(int pass, const float* __restrict__ noise, const float* __restrict__ Bvec,
       float* __restrict__ outx)
{
    extern __shared__ __align__(1024) char dsm[];

    const __nv_bfloat16* xh  = pass ? g_x2h  : g_x1h;
    const __nv_bfloat16* xl  = pass ? g_x2l  : g_x1l;
    const __nv_bfloat16* wbh = pass ? g_wb2h : g_wb1h;
    const __nv_bfloat16* wbl = pass ? g_wb2l : g_wb1l;
    const float* dm = pass ? g_d2 : g_d1;

    int tid = threadIdx.x;
    int wid = tid >> 5, lane = tid & 31;
    int wm = wid & 1, wn = wid >> 1;          // warp pos: m (co), n (px 0..3)
    int b = blockIdx.z, cb = blockIdx.y, ntile = blockIdx.x;
    int P0 = ntile * NT;
    int co_base = cb * 128;

    uint32_t sb = smem_u32(dsm);
    uint32_t sXH = sb + OFF_XH, sXL = sb + OFF_XL;

    // ldmatrix lane geometry
    int a_row = ((lane >> 3) & 1) * 8 + (lane & 7);
    int a_kb  = (lane >> 4) * 16;
    int b_n   = (lane >> 4) * 8 + (lane & 7);
    int b_kb  = ((lane >> 3) & 1) * 16;

    float acc[4][8][4];
    #pragma unroll
    for (int mi = 0; mi < 4; mi++)
        #pragma unroll
        for (int f = 0; f < 8; f++)
            #pragma unroll
            for (int r = 0; r < 4; r++) acc[mi][f][r] = 0.f;

    uint32_t rowA[4];
    #pragma unroll
    for (int mi = 0; mi < 4; mi++)
        rowA[mi] = (uint32_t)((wm * 64 + mi * 16 + a_row) * 128 + a_kb);

    const size_t xgbase = ((size_t)b * SLAB + P0) * C_;

    // staging lambdas (cp.async)
    auto stage_X = [&](int c) {
        int ci0 = c * 64;
        for (int i = tid; i < REGROWS * 8; i += 256) {
            int r = i >> 3, j = i & 7;
            size_t g = xgbase + (size_t)r * C_ + ci0 + j * 8;
            uint32_t so = swz((uint32_t)(r * 128 + j * 16));
            cpa16(sXH + so, xh + g);
            cpa16(sXL + so, xl + g);
        }
    };
    auto stage_W = [&](int c, int tap, int buf) {
        int ci0 = c * 64;
        const size_t wgbase = ((size_t)(tap * C_ + co_base)) * C_ + ci0;
        uint32_t base = sb + OFF_W + buf * WBUF;
        for (int i = tid; i < 128 * 8; i += 256) {
            int r = i >> 3, j = i & 7;
            size_t g = wgbase + (size_t)r * C_ + j * 8;
            uint32_t so = swz((uint32_t)(r * 128 + j * 16));
            cpa16(base + so, wbh + g);
            cpa16(base + 16384 + so, wbl + g);
        }
    };

    // prologue: first X chunk + first weight tap
    stage_X(0);
    stage_W(0, 0, 0);
    cpa_commit();
    cpa_wait0();
    __syncthreads();

    int cur = 0;
    for (int c = 0; c < 8; c++) {
        for (int tap = 0; tap < 9; tap++) {
            bool last = (c == 7 && tap == 8);
            // prefetch next weight tile into the other buffer
            if (!last) {
                if (tap < 8) stage_W(c, tap + 1, cur ^ 1);
                else         stage_W(c + 1, 0, cur ^ 1);
                cpa_commit();
            }

            // compute this tap from buf[cur] + resident X
            uint32_t sWH = sb + OFF_W + cur * WBUF;
            uint32_t sWL = sWH + 16384;
            int toff = (tap / 3) * QW + (tap % 3);
            uint32_t rowB[4];
            #pragma unroll
            for (int nj = 0; nj < 4; nj++)
                rowB[nj] = (uint32_t)((wn * 64 + nj * 16 + b_n + toff) * 128 + b_kb);

            #pragma unroll
            for (int ks = 0; ks < 4; ks++) {
                uint32_t kadd = ks * 32;
                uint32_t Ah[4][4], Al[4][4], Bh[4][4], Bl[4][4];
                #pragma unroll
                for (int mi = 0; mi < 4; mi++) {
                    uint32_t ro = swz(rowA[mi] + kadd);
                    ldsm4(Ah[mi], sWH + ro);
                    ldsm4(Al[mi], sWL + ro);
                }
                #pragma unroll
                for (int nj = 0; nj < 4; nj++) {
                    uint32_t ro = swz(rowB[nj] + kadd);
                    ldsm4(Bh[nj], sXH + ro);
                    ldsm4(Bl[nj], sXL + ro);
                }
                #pragma unroll
                for (int mi = 0; mi < 4; mi++) {
                    #pragma unroll
                    for (int f = 0; f < 8; f++) {
                        int bi = f >> 1, br = (f & 1) * 2;
                        mma16816(acc[mi][f], Ah[mi], Bh[bi][br], Bh[bi][br + 1]);
                        mma16816(acc[mi][f], Ah[mi], Bl[bi][br], Bl[bi][br + 1]);
                        mma16816(acc[mi][f], Al[mi], Bh[bi][br], Bh[bi][br + 1]);
                    }
                }
            }

            if (!last) {
                if (tap == 8) {
                    // chunk boundary: everyone done reading X, restage it
                    __syncthreads();
                    stage_X(c + 1);
                    cpa_commit();
                    cpa_wait0();
                    __syncthreads();
                } else {
                    cpa_wait0();       // weight prefetch landed during compute
                    __syncthreads();
                }
            }
            cur ^= 1;
        }
    }

    // ---------------- epilogue ----------------
    int g = lane >> 2, c2 = (lane & 3) * 2;
    #pragma unroll
    for (int mi = 0; mi < 4; mi++) {
        #pragma unroll
        for (int rh = 0; rh < 2; rh++) {
            int co_g = co_base + wm * 64 + mi * 16 + g + rh * 8;
            float d   = dm[b * C_ + co_g];
            float bb  = Bvec[co_g];
            float s2v = pass ? 1.f : g_s2[b * C_ + co_g];
            #pragma unroll
            for (int f = 0; f < 8; f++) {
                #pragma unroll
                for (int rl = 0; rl < 2; rl++) {
                    int col = wn * 64 + f * 8 + c2 + rl;
                    int p = P0 + col;
                    int y = p / QW;
                    int x = p - y * QW;
                    if (x < 64 && y < 64) {
                        float v = d * acc[mi][f][rh * 2 + rl] + bb * noise[b * PIX + y * 64 + x];
                        v = (v >= 0.f) ? v : SLOPE * v;
                        if (pass == 0) {
                            v *= s2v;
                            __nv_bfloat16 h = __float2bfloat16(v);
                            size_t o = ((size_t)b * SLAB + (y + 1) * QW + (x + 1)) * C_ + co_g;
                            g_x2h[o] = h;
                            g_x2l[o] = __float2bfloat16(v - __bfloat162float(h));
                        } else {
                            outx[((size_t)(b * C_ + co_g)) * PIX + y * 64 + x] = v;
                        }
                    }
                }
            }
        }
    }
}

// ---------------- toRGB 1x1 + rgb upsample + add ----------------------------
__device__ __forceinline__ float bilerp32(const float* __restrict__ p, int y, int x)
{
    const float F = 31.0f / 63.0f;
    float cy = (float)y * F, cx = (float)x * F;
    int iy0 = (int)cy, ix0 = (int)cx;
    float ty = cy - (float)iy0, tx = cx - (float)ix0;
    int iy1 = min(iy0 + 1, 31), ix1 = min(ix0 + 1, 31);
    float v00 = p[iy0 * 32 + ix0], v01 = p[iy0 * 32 + ix1];
    float v10 = p[iy1 * 32 + ix0], v11 = p[iy1 * 32 + ix1];
    float a = v00 * (1.f - ty) + v10 * ty;
    float c = v01 * (1.f - ty) + v11 * ty;
    return a * (1.f - tx) + c * tx;
}

__global__ void k_final(const float* __restrict__ y2,
                        const float* __restrict__ rgb_in,
                        const float* __restrict__ noise3,
                        const float* __restrict__ B3,
                        float* __restrict__ out_rgb)
{
    int b = blockIdx.y;
    int p = blockIdx.x * 256 + threadIdx.x;
    __shared__ float s_m3[3 * C_];
    for (int i = threadIdx.x; i < 3 * C_; i += 256) s_m3[i] = g_m3[b * 3 * C_ + i];
    __syncthreads();

    int y = p >> 6, x = p & 63;
    const float* yb = y2 + (size_t)b * C_ * PIX + p;
    float a0 = 0.f, a1 = 0.f, a2 = 0.f;
    #pragma unroll 8
    for (int ci = 0; ci < C_; ci++) {
        float v = yb[(size_t)ci * PIX];
        a0 = fmaf(s_m3[ci], v, a0);
        a1 = fmaf(s_m3[C_ + ci], v, a1);
        a2 = fmaf(s_m3[2 * C_ + ci], v, a2);
    }
    float nz = noise3[b * PIX + p];
    float a[3] = {a0, a1, a2};
    #pragma unroll
    for (int j = 0; j < 3; j++) {
        float v = a[j] + B3[j] * nz;
        v = (v >= 0.f) ? v : SLOPE * v;
        const float* rp = rgb_in + (size_t)(b * 3 + j) * 1024;
        out_rgb[(size_t)(b * 3 + j) * PIX + p] = bilerp32(rp, y, x) + v;
    }
}

// ---------------- launcher ---------------------------------------------------
extern "C" void kernel_launch(void* const* d_in, const int* in_sizes, int n_in,
                              void* d_out, int out_size)
{
    const float* x    = (const float*)d_in[0];
    const float* rgb  = (const float*)d_in[1];
    const float* w    = (const float*)d_in[2];
    const float* n1   = (const float*)d_in[3];
    const float* n2   = (const float*)d_in[4];
    const float* n3   = (const float*)d_in[5];
    const float* wt1  = (const float*)d_in[6];
    const float* A1w  = (const float*)d_in[7];
    const float* A1b  = (const float*)d_in[8];
    const float* B1   = (const float*)d_in[9];
    const float* wt2  = (const float*)d_in[10];
    const float* A2w  = (const float*)d_in[11];
    const float* A2b  = (const float*)d_in[12];
    const float* B2   = (const float*)d_in[13];
    const float* wt3  = (const float*)d_in[14];
    const float* A3w  = (const float*)d_in[15];
    const float* A3b  = (const float*)d_in[16];
    const float* B3   = (const float*)d_in[17];
    float* out = (float*)d_out;

    cudaFuncSetAttribute(k_conv, cudaFuncAttributeMaxDynamicSharedMemorySize, SMEM_CONV);

    k_styles<<<(3 * B_ * C_ + 7) / 8, 256>>>(w, A1w, A1b, A2w, A2b, A3w, A3b);
    k_wprep <<<(2 * C_ * C_ + 255) / 256, 256>>>(wt1, wt2);
    k_demod <<<(2 * B_ * C_ + 7) / 8, 256>>>();
    k_m3    <<<B_ * 3, 128>>>(wt3);
    k_zero  <<<B_ * 400, 256>>>();
    k_up    <<<dim3(64, 8, B_), 256>>>(x);
    k_conv  <<<dim3(NTILES, 4, B_), 256, SMEM_CONV>>>(0, n1, B1, out);
    k_conv  <<<dim3(NTILES, 4, B_), 256, SMEM_CONV>>>(1, n2, B2, out);
    k_final <<<dim3(PIX / 256, B_), 256>>>(out, rgb, n3, B3, out + (size_t)XEL);
}

// round 9
// speedup vs baseline: 4.4573x; 1.3735x over previous
#include <cuda_runtime.h>
#include <cuda_fp16.h>
#include <cstdint>

// ============================================================================
// BlockG via mma.sync fp16 2-term-split implicit GEMM, cp.async-pipelined.
//   conv = scale-input-by-style, shared-weight conv, scale-output-by-demod.
//   3x3 conv = 9 row-offset taps into one padded-NHWC smem region.
//   Weights W = Wh + Wl (fp16 split, 22 bits); input X single fp16.
//   W*X ~= Wh*X + Wl*X  (2 MMA terms; error = X fp16 rounding ~2^-12).
// Output: d_out[0:8*512*64*64) = x (fp32 NCHW), then [..:+8*3*64*64) = rgb.
// ============================================================================

#define B_ 8
#define C_ 512
#define PIX 4096
#define XEL (B_*C_*PIX)
#define QW 66
#define SLAB 4496
#define NT 256
#define NTILES 17
#define REGROWS 392
#define EPSV 1e-8f
#define SLOPE 0.2f

// dynamic smem layout (bytes; all 1024-aligned)
#define OFF_X  0
#define OFF_W  50176
#define WBUF   32768
#define SMEM_CONV 115712

// ---------------- device scratch ----------------
__device__ __half g_x1[B_*SLAB*C_];                      // conv1 input (padded NHWC fp16)
__device__ __half g_x2[B_*SLAB*C_];                      // conv2 input
__device__ __half g_wb1h[9*C_*C_], g_wb1l[9*C_*C_];      // [tap][co][ci] fp16 hi/lo
__device__ __half g_wb2h[9*C_*C_], g_wb2l[9*C_*C_];
__device__ float g_w2s1[C_*C_], g_w2s2[C_*C_];
__device__ float g_s1[B_*C_], g_s2[B_*C_], g_s3[B_*C_];
__device__ float g_d1[B_*C_], g_d2[B_*C_];
__device__ float g_m3[B_*3*C_];

// ---------------- helpers ----------------
__device__ __forceinline__ uint32_t smem_u32(const void* p) {
    uint32_t a;
    asm("{ .reg .u64 t; cvta.to.shared.u64 t, %1; cvt.u32.u64 %0, t; }" : "=r"(a) : "l"(p));
    return a;
}
__device__ __forceinline__ uint32_t swz(uint32_t o) { return o ^ ((o >> 3) & 0x70); }

__device__ __forceinline__ void cpa16(uint32_t dst, const void* gsrc) {
    asm volatile("cp.async.cg.shared.global [%0], [%1], 16;"
        :: "r"(dst), "l"(__cvta_generic_to_global(gsrc)) : "memory");
}
__device__ __forceinline__ void cpa_commit() {
    asm volatile("cp.async.commit_group;" ::: "memory");
}
__device__ __forceinline__ void cpa_wait0() {
    asm volatile("cp.async.wait_group 0;" ::: "memory");
}

__device__ __forceinline__ void ldsm4(uint32_t* r, uint32_t addr) {
    asm volatile("ldmatrix.sync.aligned.m8n8.x4.shared.b16 {%0,%1,%2,%3}, [%4];"
        : "=r"(r[0]), "=r"(r[1]), "=r"(r[2]), "=r"(r[3]) : "r"(addr));
}
__device__ __forceinline__ void mma16816(float* c, const uint32_t* a, uint32_t b0, uint32_t b1) {
    asm volatile("mma.sync.aligned.m16n8k16.row.col.f32.f16.f16.f32 "
        "{%0,%1,%2,%3}, {%4,%5,%6,%7}, {%8,%9}, {%0,%1,%2,%3};"
        : "+f"(c[0]), "+f"(c[1]), "+f"(c[2]), "+f"(c[3])
        : "r"(a[0]), "r"(a[1]), "r"(a[2]), "r"(a[3]), "r"(b0), "r"(b1));
}

// ---------------- styles ----------------
__global__ void k_styles(const float* __restrict__ w,
                         const float* __restrict__ A1, const float* __restrict__ b1,
                         const float* __restrict__ A2, const float* __restrict__ b2,
                         const float* __restrict__ A3, const float* __restrict__ b3)
{
    int gw = (blockIdx.x * blockDim.x + threadIdx.x) >> 5;
    int lane = threadIdx.x & 31;
    if (gw >= 3 * B_ * C_) return;
    int m = gw / (B_ * C_);
    int r = gw - m * (B_ * C_);
    int b = r >> 9, i = r & 511;
    const float* A  = (m == 0) ? A1 : (m == 1) ? A2 : A3;
    const float* bs = (m == 0) ? b1 : (m == 1) ? b2 : b3;
    float acc = 0.f;
    const float* wb = w + b * C_;
    const float* Ai = A + i * C_;
    for (int k = lane; k < C_; k += 32) acc += wb[k] * Ai[k];
    #pragma unroll
    for (int o = 16; o > 0; o >>= 1) acc += __shfl_xor_sync(0xffffffffu, acc, o);
    if (lane == 0) {
        float* out = (m == 0) ? g_s1 : (m == 1) ? g_s2 : g_s3;
        out[b * C_ + i] = acc + bs[i];
    }
}

// ---------------- weight prep: sumsq + fp16-split transpose -----------------
__global__ void k_wprep(const float* __restrict__ w1, const float* __restrict__ w2)
{
    int idx = blockIdx.x * blockDim.x + threadIdx.x;
    if (idx >= 2 * C_ * C_) return;
    int m = idx >> 18;
    int r = idx & (C_ * C_ - 1);
    int co = r >> 9, ci = r & 511;
    const float* w = m ? w2 : w1;
    float* w2s = m ? g_w2s2 : g_w2s1;
    __half* wh = m ? g_wb2h : g_wb1h;
    __half* wl = m ? g_wb2l : g_wb1l;
    const float* src = w + (size_t)(co * C_ + ci) * 9;
    float ss = 0.f;
    #pragma unroll
    for (int t = 0; t < 9; t++) {
        float v = src[t];
        ss += v * v;
        __half h = __float2half_rn(v);
        size_t o = ((size_t)t * C_ + co) * C_ + ci;
        wh[o] = h;
        wl[o] = __float2half_rn(v - __half2float(h));
    }
    w2s[co * C_ + ci] = ss;
}

// ---------------- demod ----------------
__global__ void k_demod()
{
    int gw = (blockIdx.x * blockDim.x + threadIdx.x) >> 5;
    int lane = threadIdx.x & 31;
    if (gw >= 2 * B_ * C_) return;
    int m = gw >> 12;
    int r = gw & 4095;
    int b = r >> 9, co = r & 511;
    const float* w2s = m ? g_w2s2 : g_w2s1;
    const float* s   = m ? g_s2   : g_s1;
    float acc = 0.f;
    const float* wr = w2s + co * C_;
    const float* sr = s + b * C_;
    for (int ci = lane; ci < C_; ci += 32) { float sv = sr[ci]; acc += wr[ci] * sv * sv; }
    #pragma unroll
    for (int o = 16; o > 0; o >>= 1) acc += __shfl_xor_sync(0xffffffffu, acc, o);
    if (lane == 0) {
        float* d = m ? g_d2 : g_d1;
        d[b * C_ + co] = rsqrtf(acc + EPSV);
    }
}

// ---------------- toRGB modulation ----------------
__global__ void k_m3(const float* __restrict__ w3)
{
    int b = blockIdx.x / 3, j = blockIdx.x % 3;
    __shared__ float red[128];
    __shared__ float d3s;
    int tid = threadIdx.x;
    float acc = 0.f;
    for (int ci = tid; ci < C_; ci += 128) {
        float t = w3[j * C_ + ci] * g_s3[b * C_ + ci];
        acc += t * t;
    }
    red[tid] = acc; __syncthreads();
    for (int o = 64; o > 0; o >>= 1) { if (tid < o) red[tid] += red[tid + o]; __syncthreads(); }
    if (tid == 0) d3s = rsqrtf(red[0] + EPSV);
    __syncthreads();
    float d3 = d3s;
    for (int ci = tid; ci < C_; ci += 128)
        g_m3[(b * 3 + j) * C_ + ci] = w3[j * C_ + ci] * g_s3[b * C_ + ci] * d3;
}

// ---------------- zero borders + tail of padded NHWC buffers ----------------
// rows to zero per batch: top 66, bottom 66, left 64, right 64, tail 140 = 400
__global__ void k_zero()
{
    int i = blockIdx.x % 400;
    int b = blockIdx.x / 400;
    int q;
    if (i < 66)       q = i;                          // top row (y'=0)
    else if (i < 132) q = 4290 + (i - 66);            // bottom row (y'=65)
    else if (i < 196) q = (i - 132 + 1) * QW;         // left col
    else if (i < 260) q = (i - 196 + 1) * QW + 65;    // right col
    else              q = 4356 + (i - 260);           // tail rows [4356,4496)
    size_t o = ((size_t)b * SLAB + q) * C_ / 2 + threadIdx.x;
    ((uint32_t*)g_x1)[o] = 0u;
    ((uint32_t*)g_x2)[o] = 0u;
}

// ---------------- upsample x2 + style, write fp16 NHWC ----------------------
__global__ void k_up(const float* __restrict__ xin)
{
    int y = blockIdx.x, cc = blockIdx.y, b = blockIdx.z;
    int ci0 = cc * 64;
    __shared__ float sin_[2][64][33];
    __shared__ float ss1[64];
    const float F = 31.0f / 63.0f;
    float cy = (float)y * F;
    int iy0 = (int)cy;
    float ty = cy - (float)iy0;
    int iy1 = min(iy0 + 1, 31);
    int tid = threadIdx.x;
    for (int i = tid; i < 2 * 64 * 32; i += 256) {
        int rr = i >> 11, rem = i & 2047, c = rem >> 5, xx = rem & 31;
        int iy = rr ? iy1 : iy0;
        sin_[rr][c][xx] = xin[((size_t)(b * C_ + ci0 + c) * 32 + iy) * 32 + xx];
    }
    if (tid < 64) ss1[tid] = g_s1[b * C_ + ci0 + tid];
    __syncthreads();
    #pragma unroll
    for (int j = 0; j < 16; j++) {
        int x = (tid >> 6) + j * 4;
        int c = tid & 63;
        float cx = (float)x * F;
        int ix0 = (int)cx;
        float tx = cx - (float)ix0;
        int ix1 = min(ix0 + 1, 31);
        float a0 = sin_[0][c][ix0] * (1.f - ty) + sin_[1][c][ix0] * ty;
        float a1 = sin_[0][c][ix1] * (1.f - ty) + sin_[1][c][ix1] * ty;
        float v = (a0 * (1.f - tx) + a1 * tx) * ss1[c];
        size_t o = ((size_t)b * SLAB + (y + 1) * QW + (x + 1)) * C_ + ci0 + c;
        g_x1[o] = __float2half_rn(v);
    }
}

// ---------------- mma.sync conv 3x3, cp.async pipelined ---------------------
// CTA: 128 co x 256 px, 8 warps (2m x 4n) each m64 x n64. 2-term fp16 split.
__global__ void __launch_bounds__(256)
k_conv(int pass, const float* __restrict__ noise, const float* __restrict__ Bvec,
       float* __restrict__ outx)
{
    extern __shared__ __align__(1024) char dsm[];

    const __half* xin = pass ? g_x2   : g_x1;
    const __half* wbh = pass ? g_wb2h : g_wb1h;
    const __half* wbl = pass ? g_wb2l : g_wb1l;
    const float* dm = pass ? g_d2 : g_d1;

    int tid = threadIdx.x;
    int wid = tid >> 5, lane = tid & 31;
    int wm = wid & 1, wn = wid >> 1;          // warp pos: m (co), n (px 0..3)
    int b = blockIdx.z, cb = blockIdx.y, ntile = blockIdx.x;
    int P0 = ntile * NT;
    int co_base = cb * 128;

    uint32_t sb = smem_u32(dsm);
    uint32_t sX = sb + OFF_X;

    // ldmatrix lane geometry
    int a_row = ((lane >> 3) & 1) * 8 + (lane & 7);
    int a_kb  = (lane >> 4) * 16;
    int b_n   = (lane >> 4) * 8 + (lane & 7);
    int b_kb  = ((lane >> 3) & 1) * 16;

    float acc[4][8][4];
    #pragma unroll
    for (int mi = 0; mi < 4; mi++)
        #pragma unroll
        for (int f = 0; f < 8; f++)
            #pragma unroll
            for (int r = 0; r < 4; r++) acc[mi][f][r] = 0.f;

    uint32_t rowA[4];
    #pragma unroll
    for (int mi = 0; mi < 4; mi++)
        rowA[mi] = (uint32_t)((wm * 64 + mi * 16 + a_row) * 128 + a_kb);

    const size_t xgbase = ((size_t)b * SLAB + P0) * C_;

    // staging lambdas (cp.async)
    auto stage_X = [&](int c) {
        int ci0 = c * 64;
        for (int i = tid; i < REGROWS * 8; i += 256) {
            int r = i >> 3, j = i & 7;
            size_t g = xgbase + (size_t)r * C_ + ci0 + j * 8;
            uint32_t so = swz((uint32_t)(r * 128 + j * 16));
            cpa16(sX + so, xin + g);
        }
    };
    auto stage_W = [&](int c, int tap, int buf) {
        int ci0 = c * 64;
        const size_t wgbase = ((size_t)(tap * C_ + co_base)) * C_ + ci0;
        uint32_t base = sb + OFF_W + buf * WBUF;
        for (int i = tid; i < 128 * 8; i += 256) {
            int r = i >> 3, j = i & 7;
            size_t g = wgbase + (size_t)r * C_ + j * 8;
            uint32_t so = swz((uint32_t)(r * 128 + j * 16));
            cpa16(base + so, wbh + g);
            cpa16(base + 16384 + so, wbl + g);
        }
    };

    // prologue: first X chunk + first weight tap
    stage_X(0);
    stage_W(0, 0, 0);
    cpa_commit();
    cpa_wait0();
    __syncthreads();

    int cur = 0;
    for (int c = 0; c < 8; c++) {
        for (int tap = 0; tap < 9; tap++) {
            bool last = (c == 7 && tap == 8);
            // prefetch next weight tile into the other buffer
            if (!last) {
                if (tap < 8) stage_W(c, tap + 1, cur ^ 1);
                else         stage_W(c + 1, 0, cur ^ 1);
                cpa_commit();
            }

            // compute this tap from buf[cur] + resident X
            uint32_t sWH = sb + OFF_W + cur * WBUF;
            uint32_t sWL = sWH + 16384;
            int toff = (tap / 3) * QW + (tap % 3);
            uint32_t rowB[4];
            #pragma unroll
            for (int nj = 0; nj < 4; nj++)
                rowB[nj] = (uint32_t)((wn * 64 + nj * 16 + b_n + toff) * 128 + b_kb);

            #pragma unroll
            for (int ks = 0; ks < 4; ks++) {
                uint32_t kadd = ks * 32;
                uint32_t Ah[4][4], Al[4][4], Bx[4][4];
                #pragma unroll
                for (int mi = 0; mi < 4; mi++) {
                    uint32_t ro = swz(rowA[mi] + kadd);
                    ldsm4(Ah[mi], sWH + ro);
                    ldsm4(Al[mi], sWL + ro);
                }
                #pragma unroll
                for (int nj = 0; nj < 4; nj++) {
                    uint32_t ro = swz(rowB[nj] + kadd);
                    ldsm4(Bx[nj], sX + ro);
                }
                #pragma unroll
                for (int mi = 0; mi < 4; mi++) {
                    #pragma unroll
                    for (int f = 0; f < 8; f++) {
                        int bi = f >> 1, br = (f & 1) * 2;
                        mma16816(acc[mi][f], Ah[mi], Bx[bi][br], Bx[bi][br + 1]);
                        mma16816(acc[mi][f], Al[mi], Bx[bi][br], Bx[bi][br + 1]);
                    }
                }
            }

            if (!last) {
                if (tap == 8) {
                    // chunk boundary: everyone done reading X, restage it
                    __syncthreads();
                    stage_X(c + 1);
                    cpa_commit();
                    cpa_wait0();
                    __syncthreads();
                } else {
                    cpa_wait0();       // weight prefetch landed during compute
                    __syncthreads();
                }
            }
            cur ^= 1;
        }
    }

    // ---------------- epilogue ----------------
    int g = lane >> 2, c2 = (lane & 3) * 2;
    #pragma unroll
    for (int mi = 0; mi < 4; mi++) {
        #pragma unroll
        for (int rh = 0; rh < 2; rh++) {
            int co_g = co_base + wm * 64 + mi * 16 + g + rh * 8;
            float d   = dm[b * C_ + co_g];
            float bb  = Bvec[co_g];
            float s2v = pass ? 1.f : g_s2[b * C_ + co_g];
            #pragma unroll
            for (int f = 0; f < 8; f++) {
                #pragma unroll
                for (int rl = 0; rl < 2; rl++) {
                    int col = wn * 64 + f * 8 + c2 + rl;
                    int p = P0 + col;
                    int y = p / QW;
                    int x = p - y * QW;
                    if (x < 64 && y < 64) {
                        float v = d * acc[mi][f][rh * 2 + rl] + bb * noise[b * PIX + y * 64 + x];
                        v = (v >= 0.f) ? v : SLOPE * v;
                        if (pass == 0) {
                            v *= s2v;
                            size_t o = ((size_t)b * SLAB + (y + 1) * QW + (x + 1)) * C_ + co_g;
                            g_x2[o] = __float2half_rn(v);
                        } else {
                            outx[((size_t)(b * C_ + co_g)) * PIX + y * 64 + x] = v;
                        }
                    }
                }
            }
        }
    }
}

// ---------------- toRGB 1x1 + rgb upsample + add ----------------------------
__device__ __forceinline__ float bilerp32(const float* __restrict__ p, int y, int x)
{
    const float F = 31.0f / 63.0f;
    float cy = (float)y * F, cx = (float)x * F;
    int iy0 = (int)cy, ix0 = (int)cx;
    float ty = cy - (float)iy0, tx = cx - (float)ix0;
    int iy1 = min(iy0 + 1, 31), ix1 = min(ix0 + 1, 31);
    float v00 = p[iy0 * 32 + ix0], v01 = p[iy0 * 32 + ix1];
    float v10 = p[iy1 * 32 + ix0], v11 = p[iy1 * 32 + ix1];
    float a = v00 * (1.f - ty) + v10 * ty;
    float c = v01 * (1.f - ty) + v11 * ty;
    return a * (1.f - tx) + c * tx;
}

__global__ void k_final(const float* __restrict__ y2,
                        const float* __restrict__ rgb_in,
                        const float* __restrict__ noise3,
                        const float* __restrict__ B3,
                        float* __restrict__ out_rgb)
{
    int b = blockIdx.y;
    int p = blockIdx.x * 256 + threadIdx.x;
    __shared__ float s_m3[3 * C_];
    for (int i = threadIdx.x; i < 3 * C_; i += 256) s_m3[i] = g_m3[b * 3 * C_ + i];
    __syncthreads();

    int y = p >> 6, x = p & 63;
    const float* yb = y2 + (size_t)b * C_ * PIX + p;
    float a0 = 0.f, a1 = 0.f, a2 = 0.f;
    #pragma unroll 8
    for (int ci = 0; ci < C_; ci++) {
        float v = yb[(size_t)ci * PIX];
        a0 = fmaf(s_m3[ci], v, a0);
        a1 = fmaf(s_m3[C_ + ci], v, a1);
        a2 = fmaf(s_m3[2 * C_ + ci], v, a2);
    }
    float nz = noise3[b * PIX + p];
    float a[3] = {a0, a1, a2};
    #pragma unroll
    for (int j = 0; j < 3; j++) {
        float v = a[j] + B3[j] * nz;
        v = (v >= 0.f) ? v : SLOPE * v;
        const float* rp = rgb_in + (size_t)(b * 3 + j) * 1024;
        out_rgb[(size_t)(b * 3 + j) * PIX + p] = bilerp32(rp, y, x) + v;
    }
}

// ---------------- launcher ---------------------------------------------------
extern "C" void kernel_launch(void* const* d_in, const int* in_sizes, int n_in,
                              void* d_out, int out_size)
{
    const float* x    = (const float*)d_in[0];
    const float* rgb  = (const float*)d_in[1];
    const float* w    = (const float*)d_in[2];
    const float* n1   = (const float*)d_in[3];
    const float* n2   = (const float*)d_in[4];
    const float* n3   = (const float*)d_in[5];
    const float* wt1  = (const float*)d_in[6];
    const float* A1w  = (const float*)d_in[7];
    const float* A1b  = (const float*)d_in[8];
    const float* B1   = (const float*)d_in[9];
    const float* wt2  = (const float*)d_in[10];
    const float* A2w  = (const float*)d_in[11];
    const float* A2b  = (const float*)d_in[12];
    const float* B2   = (const float*)d_in[13];
    const float* wt3  = (const float*)d_in[14];
    const float* A3w  = (const float*)d_in[15];
    const float* A3b  = (const float*)d_in[16];
    const float* B3   = (const float*)d_in[17];
    float* out = (float*)d_out;

    cudaFuncSetAttribute(k_conv, cudaFuncAttributeMaxDynamicSharedMemorySize, SMEM_CONV);

    k_styles<<<(3 * B_ * C_ + 7) / 8, 256>>>(w, A1w, A1b, A2w, A2b, A3w, A3b);
    k_wprep <<<(2 * C_ * C_ + 255) / 256, 256>>>(wt1, wt2);
    k_demod <<<(2 * B_ * C_ + 7) / 8, 256>>>();
    k_m3    <<<B_ * 3, 128>>>(wt3);
    k_zero  <<<B_ * 400, 256>>>();
    k_up    <<<dim3(64, 8, B_), 256>>>(x);
    k_conv  <<<dim3(NTILES, 4, B_), 256, SMEM_CONV>>>(0, n1, B1, out);
    k_conv  <<<dim3(NTILES, 4, B_), 256, SMEM_CONV>>>(1, n2, B2, out);
    k_final <<<dim3(PIX / 256, B_), 256>>>(out, rgb, n3, B3, out + (size_t)XEL);
}

// round 10
// speedup vs baseline: 6.9879x; 1.5677x over previous
#include <cuda_runtime.h>
#include <cuda_fp16.h>
#include <cstdint>

// ============================================================================
// BlockG via mma.sync fp16 single-term implicit GEMM, cp.async-pipelined.
//   conv = scale-input-by-style, shared-weight conv, scale-output-by-demod.
//   3x3 conv = 9 row-offset taps into one padded-NHWC smem region.
//   W and X both single fp16 (demod factors computed exactly in fp32).
// Output: d_out[0:8*512*64*64) = x (fp32 NCHW), then [..:+8*3*64*64) = rgb.
// ============================================================================

#define B_ 8
#define C_ 512
#define PIX 4096
#define XEL (B_*C_*PIX)
#define QW 66
#define SLAB 4496
#define NT 256
#define NTILES 17
#define REGROWS 392
#define EPSV 1e-8f
#define SLOPE 0.2f

// dynamic smem layout (bytes; all 1024-aligned)
#define OFF_X  0
#define OFF_W  50176
#define WBUF   16384
#define SMEM_CONV 82944

// ---------------- device scratch ----------------
__device__ __half g_x1[B_*SLAB*C_];                 // conv1 input (padded NHWC fp16)
__device__ __half g_x2[B_*SLAB*C_];                 // conv2 input
__device__ __half g_wb1[9*C_*C_], g_wb2[9*C_*C_];   // [tap][co][ci] fp16
__device__ float g_w2s1[C_*C_], g_w2s2[C_*C_];
__device__ float g_s1[B_*C_], g_s2[B_*C_], g_s3[B_*C_];
__device__ float g_d1[B_*C_], g_d2[B_*C_];
__device__ float g_m3[B_*3*C_];

// ---------------- helpers ----------------
__device__ __forceinline__ uint32_t smem_u32(const void* p) {
    uint32_t a;
    asm("{ .reg .u64 t; cvta.to.shared.u64 t, %1; cvt.u32.u64 %0, t; }" : "=r"(a) : "l"(p));
    return a;
}
__device__ __forceinline__ uint32_t swz(uint32_t o) { return o ^ ((o >> 3) & 0x70); }

__device__ __forceinline__ void cpa16(uint32_t dst, const void* gsrc) {
    asm volatile("cp.async.cg.shared.global [%0], [%1], 16;"
        :: "r"(dst), "l"(__cvta_generic_to_global(gsrc)) : "memory");
}
__device__ __forceinline__ void cpa_commit() {
    asm volatile("cp.async.commit_group;" ::: "memory");
}
__device__ __forceinline__ void cpa_wait0() {
    asm volatile("cp.async.wait_group 0;" ::: "memory");
}

__device__ __forceinline__ void ldsm4(uint32_t* r, uint32_t addr) {
    asm volatile("ldmatrix.sync.aligned.m8n8.x4.shared.b16 {%0,%1,%2,%3}, [%4];"
        : "=r"(r[0]), "=r"(r[1]), "=r"(r[2]), "=r"(r[3]) : "r"(addr));
}
__device__ __forceinline__ void mma16816(float* c, const uint32_t* a, uint32_t b0, uint32_t b1) {
    asm volatile("mma.sync.aligned.m16n8k16.row.col.f32.f16.f16.f32 "
        "{%0,%1,%2,%3}, {%4,%5,%6,%7}, {%8,%9}, {%0,%1,%2,%3};"
        : "+f"(c[0]), "+f"(c[1]), "+f"(c[2]), "+f"(c[3])
        : "r"(a[0]), "r"(a[1]), "r"(a[2]), "r"(a[3]), "r"(b0), "r"(b1));
}

// ---------------- styles ----------------
__global__ void k_styles(const float* __restrict__ w,
                         const float* __restrict__ A1, const float* __restrict__ b1,
                         const float* __restrict__ A2, const float* __restrict__ b2,
                         const float* __restrict__ A3, const float* __restrict__ b3)
{
    int gw = (blockIdx.x * blockDim.x + threadIdx.x) >> 5;
    int lane = threadIdx.x & 31;
    if (gw >= 3 * B_ * C_) return;
    int m = gw / (B_ * C_);
    int r = gw - m * (B_ * C_);
    int b = r >> 9, i = r & 511;
    const float* A  = (m == 0) ? A1 : (m == 1) ? A2 : A3;
    const float* bs = (m == 0) ? b1 : (m == 1) ? b2 : b3;
    float acc = 0.f;
    const float* wb = w + b * C_;
    const float* Ai = A + i * C_;
    for (int k = lane; k < C_; k += 32) acc += wb[k] * Ai[k];
    #pragma unroll
    for (int o = 16; o > 0; o >>= 1) acc += __shfl_xor_sync(0xffffffffu, acc, o);
    if (lane == 0) {
        float* out = (m == 0) ? g_s1 : (m == 1) ? g_s2 : g_s3;
        out[b * C_ + i] = acc + bs[i];
    }
}

// ---------------- weight prep: sumsq + fp16 transpose -----------------------
__global__ void k_wprep(const float* __restrict__ w1, const float* __restrict__ w2)
{
    int idx = blockIdx.x * blockDim.x + threadIdx.x;
    if (idx >= 2 * C_ * C_) return;
    int m = idx >> 18;
    int r = idx & (C_ * C_ - 1);
    int co = r >> 9, ci = r & 511;
    const float* w = m ? w2 : w1;
    float* w2s = m ? g_w2s2 : g_w2s1;
    __half* wh = m ? g_wb2 : g_wb1;
    const float* src = w + (size_t)(co * C_ + ci) * 9;
    float ss = 0.f;
    #pragma unroll
    for (int t = 0; t < 9; t++) {
        float v = src[t];
        ss += v * v;
        wh[((size_t)t * C_ + co) * C_ + ci] = __float2half_rn(v);
    }
    w2s[co * C_ + ci] = ss;
}

// ---------------- demod ----------------
__global__ void k_demod()
{
    int gw = (blockIdx.x * blockDim.x + threadIdx.x) >> 5;
    int lane = threadIdx.x & 31;
    if (gw >= 2 * B_ * C_) return;
    int m = gw >> 12;
    int r = gw & 4095;
    int b = r >> 9, co = r & 511;
    const float* w2s = m ? g_w2s2 : g_w2s1;
    const float* s   = m ? g_s2   : g_s1;
    float acc = 0.f;
    const float* wr = w2s + co * C_;
    const float* sr = s + b * C_;
    for (int ci = lane; ci < C_; ci += 32) { float sv = sr[ci]; acc += wr[ci] * sv * sv; }
    #pragma unroll
    for (int o = 16; o > 0; o >>= 1) acc += __shfl_xor_sync(0xffffffffu, acc, o);
    if (lane == 0) {
        float* d = m ? g_d2 : g_d1;
        d[b * C_ + co] = rsqrtf(acc + EPSV);
    }
}

// ---------------- toRGB modulation ----------------
__global__ void k_m3(const float* __restrict__ w3)
{
    int b = blockIdx.x / 3, j = blockIdx.x % 3;
    __shared__ float red[128];
    __shared__ float d3s;
    int tid = threadIdx.x;
    float acc = 0.f;
    for (int ci = tid; ci < C_; ci += 128) {
        float t = w3[j * C_ + ci] * g_s3[b * C_ + ci];
        acc += t * t;
    }
    red[tid] = acc; __syncthreads();
    for (int o = 64; o > 0; o >>= 1) { if (tid < o) red[tid] += red[tid + o]; __syncthreads(); }
    if (tid == 0) d3s = rsqrtf(red[0] + EPSV);
    __syncthreads();
    float d3 = d3s;
    for (int ci = tid; ci < C_; ci += 128)
        g_m3[(b * 3 + j) * C_ + ci] = w3[j * C_ + ci] * g_s3[b * C_ + ci] * d3;
}

// ---------------- zero borders + tail of padded NHWC buffers ----------------
// rows to zero per batch: top 66, bottom 66, left 64, right 64, tail 140 = 400
__global__ void k_zero()
{
    int i = blockIdx.x % 400;
    int b = blockIdx.x / 400;
    int q;
    if (i < 66)       q = i;                          // top row (y'=0)
    else if (i < 132) q = 4290 + (i - 66);            // bottom row (y'=65)
    else if (i < 196) q = (i - 132 + 1) * QW;         // left col
    else if (i < 260) q = (i - 196 + 1) * QW + 65;    // right col
    else              q = 4356 + (i - 260);           // tail rows [4356,4496)
    size_t o = ((size_t)b * SLAB + q) * C_ / 2 + threadIdx.x;
    ((uint32_t*)g_x1)[o] = 0u;
    ((uint32_t*)g_x2)[o] = 0u;
}

// ---------------- upsample x2 + style, write fp16 NHWC ----------------------
__global__ void k_up(const float* __restrict__ xin)
{
    int y = blockIdx.x, cc = blockIdx.y, b = blockIdx.z;
    int ci0 = cc * 64;
    __shared__ float sin_[2][64][33];
    __shared__ float ss1[64];
    const float F = 31.0f / 63.0f;
    float cy = (float)y * F;
    int iy0 = (int)cy;
    float ty = cy - (float)iy0;
    int iy1 = min(iy0 + 1, 31);
    int tid = threadIdx.x;
    for (int i = tid; i < 2 * 64 * 32; i += 256) {
        int rr = i >> 11, rem = i & 2047, c = rem >> 5, xx = rem & 31;
        int iy = rr ? iy1 : iy0;
        sin_[rr][c][xx] = xin[((size_t)(b * C_ + ci0 + c) * 32 + iy) * 32 + xx];
    }
    if (tid < 64) ss1[tid] = g_s1[b * C_ + ci0 + tid];
    __syncthreads();
    #pragma unroll
    for (int j = 0; j < 16; j++) {
        int x = (tid >> 6) + j * 4;
        int c = tid & 63;
        float cx = (float)x * F;
        int ix0 = (int)cx;
        float tx = cx - (float)ix0;
        int ix1 = min(ix0 + 1, 31);
        float a0 = sin_[0][c][ix0] * (1.f - ty) + sin_[1][c][ix0] * ty;
        float a1 = sin_[0][c][ix1] * (1.f - ty) + sin_[1][c][ix1] * ty;
        float v = (a0 * (1.f - tx) + a1 * tx) * ss1[c];
        size_t o = ((size_t)b * SLAB + (y + 1) * QW + (x + 1)) * C_ + ci0 + c;
        g_x1[o] = __float2half_rn(v);
    }
}

// ---------------- mma.sync conv 3x3, cp.async pipelined ---------------------
// CTA: 128 co x 256 px, 8 warps (2m x 4n) each m64 x n64. Single fp16 term.
__global__ void __launch_bounds__(256)
k_conv(int pass, const float* __restrict__ noise, const float* __restrict__ Bvec,
       float* __restrict__ outx)
{
    extern __shared__ __align__(1024) char dsm[];

    const __half* xin = pass ? g_x2  : g_x1;
    const __half* wb  = pass ? g_wb2 : g_wb1;
    const float* dm = pass ? g_d2 : g_d1;

    int tid = threadIdx.x;
    int wid = tid >> 5, lane = tid & 31;
    int wm = wid & 1, wn = wid >> 1;          // warp pos: m (co), n (px 0..3)
    int b = blockIdx.z, cb = blockIdx.y, ntile = blockIdx.x;
    int P0 = ntile * NT;
    int co_base = cb * 128;

    uint32_t sb = smem_u32(dsm);
    uint32_t sX = sb + OFF_X;

    // ldmatrix lane geometry
    int a_row = ((lane >> 3) & 1) * 8 + (lane & 7);
    int a_kb  = (lane >> 4) * 16;
    int b_n   = (lane >> 4) * 8 + (lane & 7);
    int b_kb  = ((lane >> 3) & 1) * 16;

    float acc[4][8][4];
    #pragma unroll
    for (int mi = 0; mi < 4; mi++)
        #pragma unroll
        for (int f = 0; f < 8; f++)
            #pragma unroll
            for (int r = 0; r < 4; r++) acc[mi][f][r] = 0.f;

    uint32_t rowA[4];
    #pragma unroll
    for (int mi = 0; mi < 4; mi++)
        rowA[mi] = (uint32_t)((wm * 64 + mi * 16 + a_row) * 128 + a_kb);

    const size_t xgbase = ((size_t)b * SLAB + P0) * C_;

    // staging lambdas (cp.async)
    auto stage_X = [&](int c) {
        int ci0 = c * 64;
        for (int i = tid; i < REGROWS * 8; i += 256) {
            int r = i >> 3, j = i & 7;
            size_t g = xgbase + (size_t)r * C_ + ci0 + j * 8;
            uint32_t so = swz((uint32_t)(r * 128 + j * 16));
            cpa16(sX + so, xin + g);
        }
    };
    auto stage_W = [&](int c, int tap, int buf) {
        int ci0 = c * 64;
        const size_t wgbase = ((size_t)(tap * C_ + co_base)) * C_ + ci0;
        uint32_t base = sb + OFF_W + buf * WBUF;
        for (int i = tid; i < 128 * 8; i += 256) {
            int r = i >> 3, j = i & 7;
            size_t g = wgbase + (size_t)r * C_ + j * 8;
            uint32_t so = swz((uint32_t)(r * 128 + j * 16));
            cpa16(base + so, wb + g);
        }
    };

    // prologue: first X chunk + first weight tap
    stage_X(0);
    stage_W(0, 0, 0);
    cpa_commit();
    cpa_wait0();
    __syncthreads();

    int cur = 0;
    for (int c = 0; c < 8; c++) {
        for (int tap = 0; tap < 9; tap++) {
            bool last = (c == 7 && tap == 8);
            // prefetch next weight tile into the other buffer
            if (!last) {
                if (tap < 8) stage_W(c, tap + 1, cur ^ 1);
                else         stage_W(c + 1, 0, cur ^ 1);
                cpa_commit();
            }

            // compute this tap from buf[cur] + resident X
            uint32_t sW = sb + OFF_W + cur * WBUF;
            int toff = (tap / 3) * QW + (tap % 3);
            uint32_t rowB[4];
            #pragma unroll
            for (int nj = 0; nj < 4; nj++)
                rowB[nj] = (uint32_t)((wn * 64 + nj * 16 + b_n + toff) * 128 + b_kb);

            #pragma unroll
            for (int ks = 0; ks < 4; ks++) {
                uint32_t kadd = ks * 32;
                uint32_t Aw[4][4], Bx[4][4];
                #pragma unroll
                for (int mi = 0; mi < 4; mi++)
                    ldsm4(Aw[mi], sW + swz(rowA[mi] + kadd));
                #pragma unroll
                for (int nj = 0; nj < 4; nj++)
                    ldsm4(Bx[nj], sX + swz(rowB[nj] + kadd));
                #pragma unroll
                for (int mi = 0; mi < 4; mi++) {
                    #pragma unroll
                    for (int f = 0; f < 8; f++) {
                        int bi = f >> 1, br = (f & 1) * 2;
                        mma16816(acc[mi][f], Aw[mi], Bx[bi][br], Bx[bi][br + 1]);
                    }
                }
            }

            if (!last) {
                if (tap == 8) {
                    // chunk boundary: everyone done reading X, restage it
                    __syncthreads();
                    stage_X(c + 1);
                    cpa_commit();
                    cpa_wait0();
                    __syncthreads();
                } else {
                    cpa_wait0();       // weight prefetch landed during compute
                    __syncthreads();
                }
            }
            cur ^= 1;
        }
    }

    // ---------------- epilogue ----------------
    int g = lane >> 2, c2 = (lane & 3) * 2;
    #pragma unroll
    for (int mi = 0; mi < 4; mi++) {
        #pragma unroll
        for (int rh = 0; rh < 2; rh++) {
            int co_g = co_base + wm * 64 + mi * 16 + g + rh * 8;
            float d   = dm[b * C_ + co_g];
            float bb  = Bvec[co_g];
            float s2v = pass ? 1.f : g_s2[b * C_ + co_g];
            #pragma unroll
            for (int f = 0; f < 8; f++) {
                #pragma unroll
                for (int rl = 0; rl < 2; rl++) {
                    int col = wn * 64 + f * 8 + c2 + rl;
                    int p = P0 + col;
                    int y = p / QW;
                    int x = p - y * QW;
                    if (x < 64 && y < 64) {
                        float v = d * acc[mi][f][rh * 2 + rl] + bb * noise[b * PIX + y * 64 + x];
                        v = (v >= 0.f) ? v : SLOPE * v;
                        if (pass == 0) {
                            v *= s2v;
                            size_t o = ((size_t)b * SLAB + (y + 1) * QW + (x + 1)) * C_ + co_g;
                            g_x2[o] = __float2half_rn(v);
                        } else {
                            outx[((size_t)(b * C_ + co_g)) * PIX + y * 64 + x] = v;
                        }
                    }
                }
            }
        }
    }
}

// ---------------- toRGB 1x1 + rgb upsample + add ----------------------------
__device__ __forceinline__ float bilerp32(const float* __restrict__ p, int y, int x)
{
    const float F = 31.0f / 63.0f;
    float cy = (float)y * F, cx = (float)x * F;
    int iy0 = (int)cy, ix0 = (int)cx;
    float ty = cy - (float)iy0, tx = cx - (float)ix0;
    int iy1 = min(iy0 + 1, 31), ix1 = min(ix0 + 1, 31);
    float v00 = p[iy0 * 32 + ix0], v01 = p[iy0 * 32 + ix1];
    float v10 = p[iy1 * 32 + ix0], v11 = p[iy1 * 32 + ix1];
    float a = v00 * (1.f - ty) + v10 * ty;
    float c = v01 * (1.f - ty) + v11 * ty;
    return a * (1.f - tx) + c * tx;
}

__global__ void k_final(const float* __restrict__ y2,
                        const float* __restrict__ rgb_in,
                        const float* __restrict__ noise3,
                        const float* __restrict__ B3,
                        float* __restrict__ out_rgb)
{
    int b = blockIdx.y;
    int p = blockIdx.x * 256 + threadIdx.x;
    __shared__ float s_m3[3 * C_];
    for (int i = threadIdx.x; i < 3 * C_; i += 256) s_m3[i] = g_m3[b * 3 * C_ + i];
    __syncthreads();

    int y = p >> 6, x = p & 63;
    const float* yb = y2 + (size_t)b * C_ * PIX + p;
    float a0 = 0.f, a1 = 0.f, a2 = 0.f;
    #pragma unroll 8
    for (int ci = 0; ci < C_; ci++) {
        float v = yb[(size_t)ci * PIX];
        a0 = fmaf(s_m3[ci], v, a0);
        a1 = fmaf(s_m3[C_ + ci], v, a1);
        a2 = fmaf(s_m3[2 * C_ + ci], v, a2);
    }
    float nz = noise3[b * PIX + p];
    float a[3] = {a0, a1, a2};
    #pragma unroll
    for (int j = 0; j < 3; j++) {
        float v = a[j] + B3[j] * nz;
        v = (v >= 0.f) ? v : SLOPE * v;
        const float* rp = rgb_in + (size_t)(b * 3 + j) * 1024;
        out_rgb[(size_t)(b * 3 + j) * PIX + p] = bilerp32(rp, y, x) + v;
    }
}

// ---------------- launcher ---------------------------------------------------
extern "C" void kernel_launch(void* const* d_in, const int* in_sizes, int n_in,
                              void* d_out, int out_size)
{
    const float* x    = (const float*)d_in[0];
    const float* rgb  = (const float*)d_in[1];
    const float* w    = (const float*)d_in[2];
    const float* n1   = (const float*)d_in[3];
    const float* n2   = (const float*)d_in[4];
    const float* n3   = (const float*)d_in[5];
    const float* wt1  = (const float*)d_in[6];
    const float* A1w  = (const float*)d_in[7];
    const float* A1b  = (const float*)d_in[8];
    const float* B1   = (const float*)d_in[9];
    const float* wt2  = (const float*)d_in[10];
    const float* A2w  = (const float*)d_in[11];
    const float* A2b  = (const float*)d_in[12];
    const float* B2   = (const float*)d_in[13];
    const float* wt3  = (const float*)d_in[14];
    const float* A3w  = (const float*)d_in[15];
    const float* A3b  = (const float*)d_in[16];
    const float* B3   = (const float*)d_in[17];
    float* out = (float*)d_out;

    cudaFuncSetAttribute(k_conv, cudaFuncAttributeMaxDynamicSharedMemorySize, SMEM_CONV);

    k_styles<<<(3 * B_ * C_ + 7) / 8, 256>>>(w, A1w, A1b, A2w, A2b, A3w, A3b);
    k_wprep <<<(2 * C_ * C_ + 255) / 256, 256>>>(wt1, wt2);
    k_demod <<<(2 * B_ * C_ + 7) / 8, 256>>>();
    k_m3    <<<B_ * 3, 128>>>(wt3);
    k_zero  <<<B_ * 400, 256>>>();
    k_up    <<<dim3(64, 8, B_), 256>>>(x);
    k_conv  <<<dim3(NTILES, 4, B_), 256, SMEM_CONV>>>(0, n1, B1, out);
    k_conv  <<<dim3(NTILES, 4, B_), 256, SMEM_CONV>>>(1, n2, B2, out);
    k_final <<<dim3(PIX / 256, B_), 256>>>(out, rgb, n3, B3, out + (size_t)XEL);
}